// round 5
// baseline (speedup 1.0000x reference)
#include <cuda_runtime.h>
#include <cstdint>

// ---------------- problem constants ----------------
#define QTOT   13294
#define BATCH  2
#define BQ     (BATCH*QTOT)   // 26588
#define DMODEL 256
#define NH     8
#define HD     32
#define NLVL   4
#define NP     4
#define DFF    1024
#define NLAYERS 6

__constant__ int c_start[4] = {0, 10000, 12500, 13125};
__constant__ int c_H[4]     = {100, 50, 25, 13};
__constant__ int c_W[4]     = {100, 50, 25, 13};

// ---------------- device scratch (no allocations allowed) ----------------
// NOTE: these are only ever touched through pointers obtained with
// cudaGetSymbolAddress — passing the symbols directly from host code gives the
// HOST shadow address, which GB300's ATS silently dereferences (wrong memory).
__device__ float g_x[BQ * DMODEL];
__device__ float g_pos[BQ * DMODEL];
__device__ float g_q[BQ * DMODEL];
__device__ float g_val[BQ * DMODEL];
__device__ float g_off[BQ * 256];
__device__ float g_logits[BQ * 128];
__device__ float g_samp[BQ * DMODEL];
__device__ float g_attnout[BQ * DMODEL];
__device__ float g_ff[BQ * DFF];
__device__ float g_ff2[BQ * DMODEL];
__device__ float g_ref[QTOT * 2];

// ---------------- helpers ----------------
__device__ __forceinline__ float wredsum(float v) {
    #pragma unroll
    for (int o = 16; o; o >>= 1) v += __shfl_xor_sync(0xffffffffu, v, o);
    return v;
}

// ---------------- flatten: src [B,D,H,W] -> x [B,Q,D]; pos + level_embed ----------------
__global__ void flatten_kernel(float* __restrict__ px, float* __restrict__ ppos,
                               const float* __restrict__ src, const float* __restrict__ pos,
                               const float* __restrict__ le, int start, int hw) {
    int idx = blockIdx.x * blockDim.x + threadIdx.x;
    int total = BATCH * hw * DMODEL;
    if (idx >= total) return;
    int d = idx & 255;
    int p = (idx >> 8) % hw;
    int b = idx / (DMODEL * hw);
    size_t sidx = ((size_t)b * DMODEL + d) * hw + p;
    size_t tok  = (size_t)b * QTOT + start + p;
    px[tok * DMODEL + d]   = src[sidx];
    ppos[tok * DMODEL + d] = pos[sidx] + le[d];
}

// ---------------- reference points ----------------
__global__ void ref_kernel(float* __restrict__ pref) {
    int q = blockIdx.x * blockDim.x + threadIdx.x;
    if (q >= QTOT) return;
    int l = 3;
    if (q < 10000) l = 0; else if (q < 12500) l = 1; else if (q < 13125) l = 2;
    int loc = q - c_start[l];
    int W = c_W[l];
    int yy = loc / W, xx = loc - yy * W;
    pref[2 * q]     = (xx + 0.5f) / (float)c_W[l];
    pref[2 * q + 1] = (yy + 0.5f) / (float)c_H[l];
}

// ---------------- q = x + pos ----------------
__global__ void addq_kernel(float* __restrict__ pq, const float* __restrict__ px,
                            const float* __restrict__ ppos) {
    int idx = blockIdx.x * blockDim.x + threadIdx.x;
    if (idx >= BQ * DMODEL) return;
    pq[idx] = px[idx] + ppos[idx];
}

// ---------------- tiled fp32 GEMM: C[M,N] = A[M,K] @ W[K,N] + bias, optional relu ----------------
#define GBM 64
#define GBN 64
#define GBK 16

template<bool RELU>
__global__ void __launch_bounds__(256) gemm_kernel(
    const float* __restrict__ A, const float* __restrict__ W,
    const float* __restrict__ bias, float* __restrict__ C,
    int M, int N, int K)
{
    __shared__ float As[GBK][GBM];
    __shared__ float Ws[GBK][GBN];
    int tid = threadIdx.x;
    int tx = tid & 15, ty = tid >> 4;
    int row0 = blockIdx.x * GBM;
    int col0 = blockIdx.y * GBN;

    float acc[4][4] = {};

    for (int kt = 0; kt < K; kt += GBK) {
        {
            int m = tid >> 2;
            int k = (tid & 3) << 2;
            int grow = row0 + m;
            float4 v = make_float4(0.f, 0.f, 0.f, 0.f);
            if (grow < M)
                v = *reinterpret_cast<const float4*>(&A[(size_t)grow * K + kt + k]);
            As[k + 0][m] = v.x; As[k + 1][m] = v.y; As[k + 2][m] = v.z; As[k + 3][m] = v.w;
        }
        {
            int k = tid >> 4;
            int n = (tid & 15) << 2;
            float4 v = *reinterpret_cast<const float4*>(&W[(size_t)(kt + k) * N + col0 + n]);
            *reinterpret_cast<float4*>(&Ws[k][n]) = v;
        }
        __syncthreads();
        #pragma unroll
        for (int k = 0; k < GBK; ++k) {
            float4 a4 = *reinterpret_cast<const float4*>(&As[k][ty << 2]);
            float4 b4 = *reinterpret_cast<const float4*>(&Ws[k][tx << 2]);
            float av[4] = {a4.x, a4.y, a4.z, a4.w};
            float bv[4] = {b4.x, b4.y, b4.z, b4.w};
            #pragma unroll
            for (int i = 0; i < 4; ++i)
                #pragma unroll
                for (int j = 0; j < 4; ++j)
                    acc[i][j] = fmaf(av[i], bv[j], acc[i][j]);
        }
        __syncthreads();
    }

    #pragma unroll
    for (int i = 0; i < 4; ++i) {
        int r = row0 + (ty << 2) + i;
        if (r >= M) continue;
        #pragma unroll
        for (int j = 0; j < 4; ++j) {
            int c = col0 + (tx << 2) + j;
            float v = acc[i][j] + bias[c];
            if (RELU) v = fmaxf(v, 0.f);
            C[(size_t)r * N + c] = v;
        }
    }
}

// ---------------- deformable attention sampling ----------------
// one warp per (b,q,h); lane = hd channel. Logits/offsets are warp-uniform
// broadcast loads; softmax over 16 (level,point) entries in registers.
__global__ void deform_kernel(const float* __restrict__ pval, const float* __restrict__ poff,
                              const float* __restrict__ plog, const float* __restrict__ pref,
                              float* __restrict__ psamp) {
    int gwarp = (blockIdx.x * blockDim.x + threadIdx.x) >> 5;
    int lane = threadIdx.x & 31;
    if (gwarp >= BATCH * QTOT * NH) return;
    int h = gwarp % NH;
    int q = (gwarp / NH) % QTOT;
    int b = gwarp / (NH * QTOT);
    size_t tok = (size_t)b * QTOT + q;

    const float* lrow = &plog[tok * 128 + h * 16];  // 16 logits for this head
    const float* orow = &poff[tok * 256 + h * 32];  // 16 (x,y) pairs

    float lg[16];
    float mx = -1e30f;
    #pragma unroll
    for (int i = 0; i < 16; ++i) { lg[i] = __ldg(&lrow[i]); mx = fmaxf(mx, lg[i]); }
    float ssum = 0.f;
    #pragma unroll
    for (int i = 0; i < 16; ++i) { lg[i] = expf(lg[i] - mx); ssum += lg[i]; }
    float inv = 1.f / ssum;

    float rx = pref[2 * q];
    float ry = pref[2 * q + 1];

    float acc = 0.f;
    #pragma unroll
    for (int p = 0; p < 16; ++p) {
        int l = p >> 2;
        float w  = lg[p] * inv;
        float ox = __ldg(&orow[2 * p]);
        float oy = __ldg(&orow[2 * p + 1]);
        int Wl = c_W[l], Hl = c_H[l];
        float fw = (float)Wl, fh = (float)Hl;
        float x = (rx + ox / fw) * fw - 0.5f;
        float y = (ry + oy / fh) * fh - 0.5f;
        float x0f = floorf(x), y0f = floorf(y);
        int x0 = (int)x0f, y0 = (int)y0f;
        float fx = x - x0f, fy = y - y0f;
        size_t base = (size_t)b * QTOT + c_start[l];
        #pragma unroll
        for (int dy = 0; dy < 2; ++dy) {
            #pragma unroll
            for (int dx = 0; dx < 2; ++dx) {
                int xi = x0 + dx, yi = y0 + dy;
                if (xi >= 0 && xi < Wl && yi >= 0 && yi < Hl) {
                    float bw = (dx ? fx : 1.f - fx) * (dy ? fy : 1.f - fy);
                    float v = pval[(base + (size_t)yi * Wl + xi) * DMODEL + h * HD + lane];
                    acc = fmaf(w * bw, v, acc);
                }
            }
        }
    }
    psamp[tok * DMODEL + h * HD + lane] = acc;
}

// ---------------- fused residual + layernorm: x = LN(x + y) ----------------
__global__ void ln_res_kernel(float* __restrict__ px, const float* __restrict__ y,
                              const float* __restrict__ g, const float* __restrict__ bb) {
    int warp = (blockIdx.x * blockDim.x + threadIdx.x) >> 5;
    int lane = threadIdx.x & 31;
    if (warp >= BQ) return;
    size_t base = (size_t)warp * DMODEL;
    float v[8];
    float s = 0.f, s2 = 0.f;
    #pragma unroll
    for (int k = 0; k < 8; ++k) {
        int d = k * 32 + lane;
        v[k] = px[base + d] + y[base + d];
        s += v[k];
        s2 += v[k] * v[k];
    }
    s = wredsum(s);
    s2 = wredsum(s2);
    float m = s * (1.f / DMODEL);
    float var = s2 * (1.f / DMODEL) - m * m;
    float rstd = rsqrtf(var + 1e-5f);
    #pragma unroll
    for (int k = 0; k < 8; ++k) {
        int d = k * 32 + lane;
        px[base + d] = (v[k] - m) * rstd * g[d] + bb[d];
    }
}

// ---------------- copy out ----------------
__global__ void copyout_kernel(float* __restrict__ out, const float* __restrict__ px) {
    int idx = blockIdx.x * blockDim.x + threadIdx.x;
    if (idx >= BQ * DMODEL) return;
    out[idx] = px[idx];
}

// ---------------- launch ----------------
extern "C" void kernel_launch(void* const* d_in, const int* in_sizes, int n_in,
                              void* d_out, int out_size) {
    (void)n_in; (void)out_size;

    // Resolve REAL device addresses of the __device__ scratch arrays.
    // (Passing the symbols directly from host passes the host shadow; GB300's
    // ATS makes that silently "work" against host memory — the round-2..4 bug.)
    float *px, *ppos, *pq, *pval, *poff, *plog, *psamp, *pattn, *pff, *pff2, *pref;
    cudaGetSymbolAddress((void**)&px,    g_x);
    cudaGetSymbolAddress((void**)&ppos,  g_pos);
    cudaGetSymbolAddress((void**)&pq,    g_q);
    cudaGetSymbolAddress((void**)&pval,  g_val);
    cudaGetSymbolAddress((void**)&poff,  g_off);
    cudaGetSymbolAddress((void**)&plog,  g_logits);
    cudaGetSymbolAddress((void**)&psamp, g_samp);
    cudaGetSymbolAddress((void**)&pattn, g_attnout);
    cudaGetSymbolAddress((void**)&pff,   g_ff);
    cudaGetSymbolAddress((void**)&pff2,  g_ff2);
    cudaGetSymbolAddress((void**)&pref,  g_ref);

    // Disambiguate input ordering at runtime via element counts.
    // dict order (src0,pos0,src1,pos1,...): sizes [5120000, 5120000, 1280000, ...]
    // signature order (src0..3, pos0..3):   sizes [5120000, 1280000, 320000, ...]
    bool interleaved = (in_sizes[1] == in_sizes[0]);
    const float* src[4];
    const float* pos[4];
    for (int i = 0; i < 4; ++i) {
        if (interleaved) {
            src[i] = (const float*)d_in[2 * i];
            pos[i] = (const float*)d_in[2 * i + 1];
        } else {
            src[i] = (const float*)d_in[i];
            pos[i] = (const float*)d_in[4 + i];
        }
    }
    const float* level_embed = (const float*)d_in[8];
    const float* Woff  = (const float*)d_in[9];
    const float* boff  = (const float*)d_in[10];
    const float* Wattn = (const float*)d_in[11];
    const float* battn = (const float*)d_in[12];
    const float* Wv    = (const float*)d_in[13];
    const float* bv    = (const float*)d_in[14];
    const float* Wo    = (const float*)d_in[15];
    const float* bo    = (const float*)d_in[16];
    const float* g1    = (const float*)d_in[17];
    const float* b1    = (const float*)d_in[18];
    const float* W1    = (const float*)d_in[19];
    const float* bb1   = (const float*)d_in[20];
    const float* W2    = (const float*)d_in[21];
    const float* bb2   = (const float*)d_in[22];
    const float* g2    = (const float*)d_in[23];
    const float* b2    = (const float*)d_in[24];
    float* out = (float*)d_out;

    const int hws[4]    = {10000, 2500, 625, 169};
    const int starts[4] = {0, 10000, 12500, 13125};

    for (int l = 0; l < 4; ++l) {
        int total = BATCH * hws[l] * DMODEL;
        flatten_kernel<<<(total + 255) / 256, 256>>>(px, ppos, src[l], pos[l],
                                                     level_embed + l * DMODEL, starts[l], hws[l]);
    }
    ref_kernel<<<(QTOT + 255) / 256, 256>>>(pref);

    const int ew_grid = (BQ * DMODEL + 255) / 256;
    const int mblocks = (BQ + GBM - 1) / GBM;                  // 416
    const int warp_grid_deform = (BATCH * QTOT * NH + 7) / 8;  // 8 warps/block
    const int warp_grid_ln = (BQ + 7) / 8;

    for (int l = 0; l < NLAYERS; ++l) {
        const float* Woff_l  = Woff  + (size_t)l * DMODEL * 256;
        const float* boff_l  = boff  + (size_t)l * 256;
        const float* Wattn_l = Wattn + (size_t)l * DMODEL * 128;
        const float* battn_l = battn + (size_t)l * 128;
        const float* Wv_l    = Wv    + (size_t)l * DMODEL * DMODEL;
        const float* bv_l    = bv    + (size_t)l * DMODEL;
        const float* Wo_l    = Wo    + (size_t)l * DMODEL * DMODEL;
        const float* bo_l    = bo    + (size_t)l * DMODEL;
        const float* W1_l    = W1    + (size_t)l * DMODEL * DFF;
        const float* bb1_l   = bb1   + (size_t)l * DFF;
        const float* W2_l    = W2    + (size_t)l * DFF * DMODEL;
        const float* bb2_l   = bb2   + (size_t)l * DMODEL;

        addq_kernel<<<ew_grid, 256>>>(pq, px, ppos);

        gemm_kernel<false><<<dim3(mblocks, 256 / GBN), 256>>>(pq, Woff_l, boff_l, poff, BQ, 256, DMODEL);
        gemm_kernel<false><<<dim3(mblocks, 128 / GBN), 256>>>(pq, Wattn_l, battn_l, plog, BQ, 128, DMODEL);
        gemm_kernel<false><<<dim3(mblocks, DMODEL / GBN), 256>>>(px, Wv_l, bv_l, pval, BQ, DMODEL, DMODEL);

        deform_kernel<<<warp_grid_deform, 256>>>(pval, poff, plog, pref, psamp);

        gemm_kernel<false><<<dim3(mblocks, DMODEL / GBN), 256>>>(psamp, Wo_l, bo_l, pattn, BQ, DMODEL, DMODEL);

        ln_res_kernel<<<warp_grid_ln, 256>>>(px, pattn, g1 + (size_t)l * DMODEL, b1 + (size_t)l * DMODEL);

        gemm_kernel<true><<<dim3(mblocks, DFF / GBN), 256>>>(px, W1_l, bb1_l, pff, BQ, DFF, DMODEL);
        gemm_kernel<false><<<dim3(mblocks, DMODEL / GBN), 256>>>(pff, W2_l, bb2_l, pff2, BQ, DMODEL, DFF);

        ln_res_kernel<<<warp_grid_ln, 256>>>(px, pff2, g2 + (size_t)l * DMODEL, b2 + (size_t)l * DMODEL);
    }

    copyout_kernel<<<ew_grid, 256>>>(out, px);
}

// round 7
// speedup vs baseline: 1.5726x; 1.5726x over previous
#include <cuda_runtime.h>
#include <cstdint>

// ---------------- problem constants ----------------
#define QTOT   13294
#define BATCH  2
#define BQ     (BATCH*QTOT)   // 26588
#define DMODEL 256
#define NH     8
#define HD     32
#define NLVL   4
#define NP     4
#define DFF    1024
#define NLAYERS 6

__constant__ int c_start[4] = {0, 10000, 12500, 13125};
__constant__ int c_H[4]     = {100, 50, 25, 13};
__constant__ int c_W[4]     = {100, 50, 25, 13};

// ---------------- device scratch ----------------
__device__ float g_x[BQ * DMODEL];
__device__ float g_pos[BQ * DMODEL];
__device__ float g_q[BQ * DMODEL];
__device__ float g_val[BQ * DMODEL];
__device__ float g_off[BQ * 256];
__device__ float g_logits[BQ * 128];
__device__ float g_samp[BQ * DMODEL];
__device__ float g_attnout[BQ * DMODEL];
__device__ float g_ff[BQ * DFF];
__device__ float g_ff2[BQ * DMODEL];
__device__ float g_ref[QTOT * 2];
// transposed weights [N,K] per layer, packed
#define WT_LAYER 753664
__device__ float g_wt[NLAYERS * WT_LAYER];

// ---------------- helpers ----------------
__device__ __forceinline__ float wredsum(float v) {
    #pragma unroll
    for (int o = 16; o; o >>= 1) v += __shfl_xor_sync(0xffffffffu, v, o);
    return v;
}
__device__ __forceinline__ uint32_t smem_u32(const void* p) {
    uint32_t a;
    asm("{ .reg .u64 t; cvta.to.shared.u64 t, %1; cvt.u32.u64 %0, t; }" : "=r"(a) : "l"(p));
    return a;
}
__device__ __forceinline__ uint32_t f2tf32(float f) {
    uint32_t o;
    asm("cvt.rna.tf32.f32 %0, %1;" : "=r"(o) : "f"(f));
    return o;
}
__device__ __forceinline__ void cpasync16(uint32_t dst, const void* src, bool pred) {
    int sz = pred ? 16 : 0;
    asm volatile("cp.async.cg.shared.global [%0], [%1], 16, %2;"
                 :: "r"(dst), "l"(src), "r"(sz) : "memory");
}
#define CP_COMMIT() asm volatile("cp.async.commit_group;" ::: "memory")
#define CP_WAIT0()  asm volatile("cp.async.wait_group 0;" ::: "memory")
#define CP_WAIT1()  asm volatile("cp.async.wait_group 1;" ::: "memory")

__device__ __forceinline__ void mma16n8k8(float* c, const uint32_t* a, const uint32_t* b) {
    asm volatile(
        "mma.sync.aligned.m16n8k8.row.col.f32.tf32.tf32.f32 "
        "{%0,%1,%2,%3}, {%4,%5,%6,%7}, {%8,%9}, {%0,%1,%2,%3};"
        : "+f"(c[0]), "+f"(c[1]), "+f"(c[2]), "+f"(c[3])
        : "r"(a[0]), "r"(a[1]), "r"(a[2]), "r"(a[3]), "r"(b[0]), "r"(b[1]));
}

// ---------------- flatten ----------------
__global__ void flatten_kernel(float* __restrict__ px, float* __restrict__ ppos,
                               const float* __restrict__ src, const float* __restrict__ pos,
                               const float* __restrict__ le, int start, int hw) {
    int idx = blockIdx.x * blockDim.x + threadIdx.x;
    int total = BATCH * hw * DMODEL;
    if (idx >= total) return;
    int d = idx & 255;
    int p = (idx >> 8) % hw;
    int b = idx / (DMODEL * hw);
    size_t sidx = ((size_t)b * DMODEL + d) * hw + p;
    size_t tok  = (size_t)b * QTOT + start + p;
    px[tok * DMODEL + d]   = src[sidx];
    ppos[tok * DMODEL + d] = pos[sidx] + le[d];
}

// ---------------- reference points ----------------
__global__ void ref_kernel(float* __restrict__ pref) {
    int q = blockIdx.x * blockDim.x + threadIdx.x;
    if (q >= QTOT) return;
    int l = 3;
    if (q < 10000) l = 0; else if (q < 12500) l = 1; else if (q < 13125) l = 2;
    int loc = q - c_start[l];
    int W = c_W[l];
    int yy = loc / W, xx = loc - yy * W;
    pref[2 * q]     = (xx + 0.5f) / (float)c_W[l];
    pref[2 * q + 1] = (yy + 0.5f) / (float)c_H[l];
}

// ---------------- q = x + pos ----------------
__global__ void addq_kernel(float* __restrict__ pq, const float* __restrict__ px,
                            const float* __restrict__ ppos) {
    int idx = blockIdx.x * blockDim.x + threadIdx.x;
    if (idx >= BQ * DMODEL) return;
    pq[idx] = px[idx] + ppos[idx];
}

// ---------------- weight transpose: out[N,K] = in[K,N]^T ----------------
__global__ void transpose_kernel(float* __restrict__ out, const float* __restrict__ in,
                                 int K, int N) {
    int idx = blockIdx.x * blockDim.x + threadIdx.x;
    if (idx >= N * K) return;
    int n = idx / K, k = idx - n * K;
    out[idx] = in[(size_t)k * N + n];
}

// ---------------- tf32 mma.sync GEMM: C[M,N] = A[M,K] @ Bt[N,K]^T + bias ----------------
// block tile 128x64, 8 warps (4M x 2N), warp tile 32x32, K chunks of 32,
// cp.async double buffering. Smem stride 36 -> conflict-free fragment LDS.
#define TM 128
#define TN 64
#define KC 32
#define ASTR 36
#define BSTR 36
#define A_BUF_FLOATS (TM * ASTR)          // 4608
#define B_BUF_FLOATS (TN * BSTR)          // 2304
#define SMEM_FLOATS  (2 * A_BUF_FLOATS + 2 * B_BUF_FLOATS)   // 13824 -> 55296 B

template<bool RELU>
__global__ void __launch_bounds__(256) gemm_mma_kernel(
    const float* __restrict__ A, const float* __restrict__ Bt,
    const float* __restrict__ bias, float* __restrict__ C,
    int M, int N, int K)
{
    extern __shared__ float smem[];
    float* Abuf[2] = { smem, smem + A_BUF_FLOATS };
    float* Bbuf[2] = { smem + 2 * A_BUF_FLOATS, smem + 2 * A_BUF_FLOATS + B_BUF_FLOATS };

    int tid = threadIdx.x;
    int wid = tid >> 5, lane = tid & 31;
    int wm = wid & 3, wn = wid >> 2;           // 4 M-warps x 2 N-warps
    int m0 = blockIdx.x * TM;
    int n0 = blockIdx.y * TN;
    int NC = K / KC;

    // staging indices
    int ar = tid >> 1, ah = tid & 1;           // A: row, 16-float half
    int br = tid >> 2, bqd = tid & 3;          // B: row, 8-float quarter

    uint32_t aDst[2], bDst[2];
    #pragma unroll
    for (int s = 0; s < 2; ++s) {
        aDst[s] = smem_u32(&Abuf[s][ar * ASTR + ah * 16]);
        bDst[s] = smem_u32(&Bbuf[s][br * BSTR + bqd * 8]);
    }

    int aRowG = m0 + ar;
    bool aOK = aRowG < M;
    int aRowC = aOK ? aRowG : (M - 1);

    float acc[2][4][4];
    #pragma unroll
    for (int i = 0; i < 2; ++i)
        #pragma unroll
        for (int j = 0; j < 4; ++j)
            #pragma unroll
            for (int r = 0; r < 4; ++r) acc[i][j][r] = 0.f;

    // stage chunk 0
    {
        const float* as = &A[(size_t)aRowC * K + 0 * KC + ah * 16];
        cpasync16(aDst[0] + 0,  as + 0, aOK);
        cpasync16(aDst[0] + 16, as + 4, aOK);
        cpasync16(aDst[0] + 32, as + 8, aOK);
        cpasync16(aDst[0] + 48, as + 12, aOK);
        const float* bs = &Bt[(size_t)(n0 + br) * K + 0 * KC + bqd * 8];
        cpasync16(bDst[0] + 0,  bs + 0, true);
        cpasync16(bDst[0] + 16, bs + 4, true);
        CP_COMMIT();
    }

    for (int c = 0; c < NC; ++c) {
        int cur = c & 1;
        if (c + 1 < NC) {
            int nxt = (c + 1) & 1;
            const float* as = &A[(size_t)aRowC * K + (c + 1) * KC + ah * 16];
            cpasync16(aDst[nxt] + 0,  as + 0, aOK);
            cpasync16(aDst[nxt] + 16, as + 4, aOK);
            cpasync16(aDst[nxt] + 32, as + 8, aOK);
            cpasync16(aDst[nxt] + 48, as + 12, aOK);
            const float* bs = &Bt[(size_t)(n0 + br) * K + (c + 1) * KC + bqd * 8];
            cpasync16(bDst[nxt] + 0,  bs + 0, true);
            cpasync16(bDst[nxt] + 16, bs + 4, true);
            CP_COMMIT();
            CP_WAIT1();              // chunk c arrived
        } else {
            CP_WAIT0();
        }
        __syncthreads();

        const float* As = Abuf[cur];
        const float* Bs = Bbuf[cur];
        int arow = wm * 32 + (lane >> 2);
        int bcolbase = wn * 32 + (lane >> 2);
        int kcol = lane & 3;

        #pragma unroll
        for (int ks = 0; ks < 4; ++ks) {
            int k0 = ks * 8 + kcol;
            uint32_t af[2][4];
            #pragma unroll
            for (int mt = 0; mt < 2; ++mt) {
                int r = arow + mt * 16;
                af[mt][0] = f2tf32(As[r * ASTR + k0]);
                af[mt][1] = f2tf32(As[(r + 8) * ASTR + k0]);
                af[mt][2] = f2tf32(As[r * ASTR + k0 + 4]);
                af[mt][3] = f2tf32(As[(r + 8) * ASTR + k0 + 4]);
            }
            uint32_t bf[4][2];
            #pragma unroll
            for (int nt = 0; nt < 4; ++nt) {
                int n = bcolbase + nt * 8;
                bf[nt][0] = f2tf32(Bs[n * BSTR + k0]);
                bf[nt][1] = f2tf32(Bs[n * BSTR + k0 + 4]);
            }
            #pragma unroll
            for (int mt = 0; mt < 2; ++mt)
                #pragma unroll
                for (int nt = 0; nt < 4; ++nt)
                    mma16n8k8(acc[mt][nt], af[mt], bf[nt]);
        }
        __syncthreads();
    }

    // epilogue
    #pragma unroll
    for (int mt = 0; mt < 2; ++mt) {
        int r0 = m0 + wm * 32 + mt * 16 + (lane >> 2);
        int r1 = r0 + 8;
        #pragma unroll
        for (int nt = 0; nt < 4; ++nt) {
            int cb = n0 + wn * 32 + nt * 8 + 2 * (lane & 3);
            float b0 = bias[cb], b1 = bias[cb + 1];
            if (r0 < M) {
                float v0 = acc[mt][nt][0] + b0;
                float v1 = acc[mt][nt][1] + b1;
                if (RELU) { v0 = fmaxf(v0, 0.f); v1 = fmaxf(v1, 0.f); }
                *reinterpret_cast<float2*>(&C[(size_t)r0 * N + cb]) = make_float2(v0, v1);
            }
            if (r1 < M) {
                float v2 = acc[mt][nt][2] + b0;
                float v3 = acc[mt][nt][3] + b1;
                if (RELU) { v2 = fmaxf(v2, 0.f); v3 = fmaxf(v3, 0.f); }
                *reinterpret_cast<float2*>(&C[(size_t)r1 * N + cb]) = make_float2(v2, v3);
            }
        }
    }
}

// ---------------- deformable attention sampling ----------------
__global__ void deform_kernel(const float* __restrict__ pval, const float* __restrict__ poff,
                              const float* __restrict__ plog, const float* __restrict__ pref,
                              float* __restrict__ psamp) {
    int gwarp = (blockIdx.x * blockDim.x + threadIdx.x) >> 5;
    int lane = threadIdx.x & 31;
    if (gwarp >= BATCH * QTOT * NH) return;
    int h = gwarp % NH;
    int q = (gwarp / NH) % QTOT;
    int b = gwarp / (NH * QTOT);
    size_t tok = (size_t)b * QTOT + q;

    const float* lrow = &plog[tok * 128 + h * 16];
    const float* orow = &poff[tok * 256 + h * 32];

    float lg[16];
    float mx = -1e30f;
    #pragma unroll
    for (int i = 0; i < 16; ++i) { lg[i] = __ldg(&lrow[i]); mx = fmaxf(mx, lg[i]); }
    float ssum = 0.f;
    #pragma unroll
    for (int i = 0; i < 16; ++i) { lg[i] = expf(lg[i] - mx); ssum += lg[i]; }
    float inv = 1.f / ssum;

    float rx = pref[2 * q];
    float ry = pref[2 * q + 1];

    float acc = 0.f;
    #pragma unroll
    for (int p = 0; p < 16; ++p) {
        int l = p >> 2;
        float w  = lg[p] * inv;
        float ox = __ldg(&orow[2 * p]);
        float oy = __ldg(&orow[2 * p + 1]);
        int Wl = c_W[l], Hl = c_H[l];
        float fw = (float)Wl, fh = (float)Hl;
        float x = (rx + ox / fw) * fw - 0.5f;
        float y = (ry + oy / fh) * fh - 0.5f;
        float x0f = floorf(x), y0f = floorf(y);
        int x0 = (int)x0f, y0 = (int)y0f;
        float fx = x - x0f, fy = y - y0f;
        size_t base = (size_t)b * QTOT + c_start[l];
        #pragma unroll
        for (int dy = 0; dy < 2; ++dy) {
            #pragma unroll
            for (int dx = 0; dx < 2; ++dx) {
                int xi = x0 + dx, yi = y0 + dy;
                if (xi >= 0 && xi < Wl && yi >= 0 && yi < Hl) {
                    float bw = (dx ? fx : 1.f - fx) * (dy ? fy : 1.f - fy);
                    float v = pval[(base + (size_t)yi * Wl + xi) * DMODEL + h * HD + lane];
                    acc = fmaf(w * bw, v, acc);
                }
            }
        }
    }
    psamp[tok * DMODEL + h * HD + lane] = acc;
}

// ---------------- fused residual + layernorm ----------------
__global__ void ln_res_kernel(float* __restrict__ px, const float* __restrict__ y,
                              const float* __restrict__ g, const float* __restrict__ bb) {
    int warp = (blockIdx.x * blockDim.x + threadIdx.x) >> 5;
    int lane = threadIdx.x & 31;
    if (warp >= BQ) return;
    size_t base = (size_t)warp * DMODEL;
    float v[8];
    float s = 0.f, s2 = 0.f;
    #pragma unroll
    for (int k = 0; k < 8; ++k) {
        int d = k * 32 + lane;
        v[k] = px[base + d] + y[base + d];
        s += v[k];
        s2 += v[k] * v[k];
    }
    s = wredsum(s);
    s2 = wredsum(s2);
    float m = s * (1.f / DMODEL);
    float var = s2 * (1.f / DMODEL) - m * m;
    float rstd = rsqrtf(var + 1e-5f);
    #pragma unroll
    for (int k = 0; k < 8; ++k) {
        int d = k * 32 + lane;
        px[base + d] = (v[k] - m) * rstd * g[d] + bb[d];
    }
}

// ---------------- copy out ----------------
__global__ void copyout_kernel(float* __restrict__ out, const float* __restrict__ px) {
    int idx = blockIdx.x * blockDim.x + threadIdx.x;
    if (idx >= BQ * DMODEL) return;
    out[idx] = px[idx];
}

// ---------------- launch ----------------
extern "C" void kernel_launch(void* const* d_in, const int* in_sizes, int n_in,
                              void* d_out, int out_size) {
    (void)n_in; (void)out_size;

    float *px, *ppos, *pq, *pval, *poff, *plog, *psamp, *pattn, *pff, *pff2, *pref, *pwt;
    cudaGetSymbolAddress((void**)&px,    g_x);
    cudaGetSymbolAddress((void**)&ppos,  g_pos);
    cudaGetSymbolAddress((void**)&pq,    g_q);
    cudaGetSymbolAddress((void**)&pval,  g_val);
    cudaGetSymbolAddress((void**)&poff,  g_off);
    cudaGetSymbolAddress((void**)&plog,  g_logits);
    cudaGetSymbolAddress((void**)&psamp, g_samp);
    cudaGetSymbolAddress((void**)&pattn, g_attnout);
    cudaGetSymbolAddress((void**)&pff,   g_ff);
    cudaGetSymbolAddress((void**)&pff2,  g_ff2);
    cudaGetSymbolAddress((void**)&pref,  g_ref);
    cudaGetSymbolAddress((void**)&pwt,   g_wt);

    const int SMEM_BYTES = SMEM_FLOATS * 4;   // 55296
    cudaFuncSetAttribute(gemm_mma_kernel<false>,
                         cudaFuncAttributeMaxDynamicSharedMemorySize, SMEM_BYTES);
    cudaFuncSetAttribute(gemm_mma_kernel<true>,
                         cudaFuncAttributeMaxDynamicSharedMemorySize, SMEM_BYTES);

    bool interleaved = (in_sizes[1] == in_sizes[0]);
    const float* src[4];
    const float* pos[4];
    for (int i = 0; i < 4; ++i) {
        if (interleaved) {
            src[i] = (const float*)d_in[2 * i];
            pos[i] = (const float*)d_in[2 * i + 1];
        } else {
            src[i] = (const float*)d_in[i];
            pos[i] = (const float*)d_in[4 + i];
        }
    }
    const float* level_embed = (const float*)d_in[8];
    const float* Woff  = (const float*)d_in[9];
    const float* boff  = (const float*)d_in[10];
    const float* Wattn = (const float*)d_in[11];
    const float* battn = (const float*)d_in[12];
    const float* Wv    = (const float*)d_in[13];
    const float* bv    = (const float*)d_in[14];
    const float* Wo    = (const float*)d_in[15];
    const float* bo    = (const float*)d_in[16];
    const float* g1    = (const float*)d_in[17];
    const float* b1    = (const float*)d_in[18];
    const float* W1    = (const float*)d_in[19];
    const float* bb1   = (const float*)d_in[20];
    const float* W2    = (const float*)d_in[21];
    const float* bb2   = (const float*)d_in[22];
    const float* g2    = (const float*)d_in[23];
    const float* b2    = (const float*)d_in[24];
    float* out = (float*)d_out;

    const int hws[4]    = {10000, 2500, 625, 169};
    const int starts[4] = {0, 10000, 12500, 13125};

    for (int l = 0; l < 4; ++l) {
        int total = BATCH * hws[l] * DMODEL;
        flatten_kernel<<<(total + 255) / 256, 256>>>(px, ppos, src[l], pos[l],
                                                     level_embed + l * DMODEL, starts[l], hws[l]);
    }
    ref_kernel<<<(QTOT + 255) / 256, 256>>>(pref);

    const int OFF_WOFF = 0;
    const int OFF_WATTN = 65536;
    const int OFF_WV = 98304;
    const int OFF_WO = 163840;
    const int OFF_W1 = 229376;
    const int OFF_W2 = 491520;

    for (int l = 0; l < NLAYERS; ++l) {
        float* wt = pwt + (size_t)l * WT_LAYER;
        transpose_kernel<<<(65536 + 255) / 256, 256>>>(wt + OFF_WOFF,  Woff  + (size_t)l * 65536, 256, 256);
        transpose_kernel<<<(32768 + 255) / 256, 256>>>(wt + OFF_WATTN, Wattn + (size_t)l * 32768, 256, 128);
        transpose_kernel<<<(65536 + 255) / 256, 256>>>(wt + OFF_WV,    Wv    + (size_t)l * 65536, 256, 256);
        transpose_kernel<<<(65536 + 255) / 256, 256>>>(wt + OFF_WO,    Wo    + (size_t)l * 65536, 256, 256);
        transpose_kernel<<<(262144 + 255) / 256, 256>>>(wt + OFF_W1,   W1    + (size_t)l * 262144, 256, 1024);
        transpose_kernel<<<(262144 + 255) / 256, 256>>>(wt + OFF_W2,   W2    + (size_t)l * 262144, 1024, 256);
    }

    const int ew_grid = (BQ * DMODEL + 255) / 256;
    const int mblocks = (BQ + TM - 1) / TM;                    // 208
    const int warp_grid_deform = (BATCH * QTOT * NH + 7) / 8;
    const int warp_grid_ln = (BQ + 7) / 8;

    for (int l = 0; l < NLAYERS; ++l) {
        const float* wt = pwt + (size_t)l * WT_LAYER;
        const float* boff_l  = boff  + (size_t)l * 256;
        const float* battn_l = battn + (size_t)l * 128;
        const float* bv_l    = bv    + (size_t)l * DMODEL;
        const float* bo_l    = bo    + (size_t)l * DMODEL;
        const float* bb1_l   = bb1   + (size_t)l * DFF;
        const float* bb2_l   = bb2   + (size_t)l * DMODEL;

        addq_kernel<<<ew_grid, 256>>>(pq, px, ppos);

        gemm_mma_kernel<false><<<dim3(mblocks, 256 / TN), 256, SMEM_BYTES>>>(
            pq, wt + OFF_WOFF, boff_l, poff, BQ, 256, 256);
        gemm_mma_kernel<false><<<dim3(mblocks, 128 / TN), 256, SMEM_BYTES>>>(
            pq, wt + OFF_WATTN, battn_l, plog, BQ, 128, 256);
        gemm_mma_kernel<false><<<dim3(mblocks, 256 / TN), 256, SMEM_BYTES>>>(
            px, wt + OFF_WV, bv_l, pval, BQ, 256, 256);

        deform_kernel<<<warp_grid_deform, 256>>>(pval, poff, plog, pref, psamp);

        gemm_mma_kernel<false><<<dim3(mblocks, 256 / TN), 256, SMEM_BYTES>>>(
            psamp, wt + OFF_WO, bo_l, pattn, BQ, 256, 256);

        ln_res_kernel<<<warp_grid_ln, 256>>>(px, pattn, g1 + (size_t)l * DMODEL, b1 + (size_t)l * DMODEL);

        gemm_mma_kernel<true><<<dim3(mblocks, DFF / TN), 256, SMEM_BYTES>>>(
            px, wt + OFF_W1, bb1_l, pff, BQ, DFF, 256);
        gemm_mma_kernel<false><<<dim3(mblocks, 256 / TN), 256, SMEM_BYTES>>>(
            pff, wt + OFF_W2, bb2_l, pff2, BQ, 256, 1024);

        ln_res_kernel<<<warp_grid_ln, 256>>>(px, pff2, g2 + (size_t)l * DMODEL, b2 + (size_t)l * DMODEL);
    }

    copyout_kernel<<<ew_grid, 256>>>(out, px);
}

// round 8
// speedup vs baseline: 2.0442x; 1.2999x over previous
#include <cuda_runtime.h>
#include <cuda_fp16.h>
#include <cstdint>

// ---------------- problem constants ----------------
#define QTOT   13294
#define BATCH  2
#define BQ     (BATCH*QTOT)   // 26588
#define DMODEL 256
#define NH     8
#define HD     32
#define DFF    1024
#define NLAYERS 6

__constant__ int c_start[4] = {0, 10000, 12500, 13125};
__constant__ int c_H[4]     = {100, 50, 25, 13};
__constant__ int c_W[4]     = {100, 50, 25, 13};

// ---------------- device scratch ----------------
__device__ float  g_x[BQ * DMODEL];        // fp32 residual stream
__device__ float  g_pos[BQ * DMODEL];
__device__ float  g_off[BQ * 256];
__device__ float  g_logits[BQ * 128];
__device__ float  g_attnout[BQ * DMODEL];
__device__ float  g_ff2[BQ * DMODEL];
__device__ float  g_ref[QTOT * 2];
__device__ __half g_xh[BQ * DMODEL];       // fp16 copy of x (GEMM A)
__device__ __half g_qh[BQ * DMODEL];       // fp16 q
__device__ __half g_valh[BQ * DMODEL];     // fp16 values
__device__ __half g_samph[BQ * DMODEL];    // fp16 sampled
__device__ __half g_ffh[BQ * DFF];         // fp16 FF hidden
#define WT_LAYER 753664
__device__ __half g_wt[NLAYERS * WT_LAYER]; // transposed fp16 weights [N,K]

// ---------------- helpers ----------------
__device__ __forceinline__ float wredsum(float v) {
    #pragma unroll
    for (int o = 16; o; o >>= 1) v += __shfl_xor_sync(0xffffffffu, v, o);
    return v;
}
__device__ __forceinline__ uint32_t smem_u32(const void* p) {
    uint32_t a;
    asm("{ .reg .u64 t; cvta.to.shared.u64 t, %1; cvt.u32.u64 %0, t; }" : "=r"(a) : "l"(p));
    return a;
}
#define LDSM4(r, addr) \
    asm volatile("ldmatrix.sync.aligned.m8n8.x4.shared.b16 {%0,%1,%2,%3}, [%4];" \
        : "=r"((r)[0]), "=r"((r)[1]), "=r"((r)[2]), "=r"((r)[3]) : "r"(addr))

__device__ __forceinline__ void mma_f16(float* c, const uint32_t* a, const uint32_t* b) {
    asm volatile(
        "mma.sync.aligned.m16n8k16.row.col.f32.f16.f16.f32 "
        "{%0,%1,%2,%3}, {%4,%5,%6,%7}, {%8,%9}, {%0,%1,%2,%3};"
        : "+f"(c[0]), "+f"(c[1]), "+f"(c[2]), "+f"(c[3])
        : "r"(a[0]), "r"(a[1]), "r"(a[2]), "r"(a[3]), "r"(b[0]), "r"(b[1]));
}

// ---------------- flatten: src [B,D,H,W] -> x (f32 + f16); pos + level_embed ----------------
__global__ void flatten_kernel(float* __restrict__ px, __half* __restrict__ pxh,
                               float* __restrict__ ppos,
                               const float* __restrict__ src, const float* __restrict__ pos,
                               const float* __restrict__ le, int start, int hw) {
    int idx = blockIdx.x * blockDim.x + threadIdx.x;
    int total = BATCH * hw * DMODEL;
    if (idx >= total) return;
    int d = idx & 255;
    int p = (idx >> 8) % hw;
    int b = idx / (DMODEL * hw);
    size_t sidx = ((size_t)b * DMODEL + d) * hw + p;
    size_t tok  = (size_t)b * QTOT + start + p;
    float v = src[sidx];
    px[tok * DMODEL + d]  = v;
    pxh[tok * DMODEL + d] = __float2half_rn(v);
    ppos[tok * DMODEL + d] = pos[sidx] + le[d];
}

// ---------------- reference points ----------------
__global__ void ref_kernel(float* __restrict__ pref) {
    int q = blockIdx.x * blockDim.x + threadIdx.x;
    if (q >= QTOT) return;
    int l = 3;
    if (q < 10000) l = 0; else if (q < 12500) l = 1; else if (q < 13125) l = 2;
    int loc = q - c_start[l];
    int W = c_W[l];
    int yy = loc / W, xx = loc - yy * W;
    pref[2 * q]     = (xx + 0.5f) / (float)c_W[l];
    pref[2 * q + 1] = (yy + 0.5f) / (float)c_H[l];
}

// ---------------- q = half(x + pos) ----------------
__global__ void addq_kernel(__half* __restrict__ pqh, const float* __restrict__ px,
                            const float* __restrict__ ppos) {
    int idx = blockIdx.x * blockDim.x + threadIdx.x;
    if (idx >= BQ * DMODEL) return;
    pqh[idx] = __float2half_rn(px[idx] + ppos[idx]);
}

// ---------------- weight transpose+convert: out[N,K] = half(in[K,N]^T) ----------------
__global__ void transpose_kernel(__half* __restrict__ out, const float* __restrict__ in,
                                 int K, int N) {
    int idx = blockIdx.x * blockDim.x + threadIdx.x;
    if (idx >= N * K) return;
    int n = idx / K, k = idx - n * K;
    out[idx] = __float2half_rn(in[(size_t)k * N + n]);
}

// ---------------- fp16 mma.sync GEMM: C[M,N] = A[M,K] @ Bt[N,K]^T + bias ----------------
// block 128x64, 8 warps (4M x 2N), warp tile 32x32, mma m16n8k16, KC=32,
// reg-double-buffered staging, ldmatrix fragments, padded stride 40 halves.
#define TM 128
#define TN 64
#define ASTR 40
#define BSTR 40

template<bool RELU, bool HALF_OUT>
__global__ void __launch_bounds__(256) gemm_h_kernel(
    const __half* __restrict__ A, const __half* __restrict__ Bt,
    const float* __restrict__ bias, void* __restrict__ Cv,
    int M, int N, int K)
{
    __shared__ __align__(16) __half smA[2][TM * ASTR];
    __shared__ __align__(16) __half smB[2][TN * BSTR];

    int tid = threadIdx.x;
    int wid = tid >> 5, lane = tid & 31;
    int wm = wid & 3, wn = wid >> 2;
    int m0 = blockIdx.x * TM;
    int n0 = blockIdx.y * TN;
    int NC = K >> 5;

    // staging indices: A 128 rows x 32 halves, 2 thr/row (16 halves each)
    int arow = tid >> 1, ahalf = tid & 1;
    // B 64 rows x 32 halves, 4 thr/row (8 halves each)
    int brow = tid >> 2, bq = tid & 3;
    int aRowG = m0 + arow;
    int aRowC = (aRowG < M) ? aRowG : (M - 1);

    float acc[2][4][4];
    #pragma unroll
    for (int i = 0; i < 2; ++i)
        #pragma unroll
        for (int j = 0; j < 4; ++j)
            #pragma unroll
            for (int r = 0; r < 4; ++r) acc[i][j][r] = 0.f;

    // preload chunk 0
    const uint4* aG = (const uint4*)&A[(size_t)aRowC * K + ahalf * 16];
    const uint4* bG = (const uint4*)&Bt[(size_t)(n0 + brow) * K + bq * 8];
    uint4 ra0 = aG[0], ra1 = aG[1];
    uint4 rb  = bG[0];

    // fragment lane mapping
    int sub = lane >> 3, lrow = lane & 7;

    for (int c = 0; c < NC; ++c) {
        int buf = c & 1;
        // store staged chunk
        *reinterpret_cast<uint4*>(&smA[buf][arow * ASTR + ahalf * 16])     = ra0;
        *reinterpret_cast<uint4*>(&smA[buf][arow * ASTR + ahalf * 16 + 8]) = ra1;
        *reinterpret_cast<uint4*>(&smB[buf][brow * BSTR + bq * 8])         = rb;
        if (c + 1 < NC) {
            const uint4* aGn = (const uint4*)&A[(size_t)aRowC * K + (c + 1) * 32 + ahalf * 16];
            const uint4* bGn = (const uint4*)&Bt[(size_t)(n0 + brow) * K + (c + 1) * 32 + bq * 8];
            ra0 = aGn[0]; ra1 = aGn[1]; rb = bGn[0];
        }
        __syncthreads();

        const __half* As = smA[buf];
        const __half* Bs = smB[buf];
        #pragma unroll
        for (int ks = 0; ks < 2; ++ks) {
            uint32_t af[2][4];
            #pragma unroll
            for (int mt = 0; mt < 2; ++mt) {
                int r = wm * 32 + mt * 16 + ((sub & 1) << 3) + lrow;
                int col = ks * 16 + ((sub >> 1) << 3);
                LDSM4(af[mt], smem_u32(&As[r * ASTR + col]));
            }
            uint32_t bf[4][2];
            #pragma unroll
            for (int g = 0; g < 2; ++g) {
                int nr = wn * 32 + ((g * 2 + (sub >> 1)) << 3) + lrow;
                int col = ks * 16 + ((sub & 1) << 3);
                uint32_t t[4];
                LDSM4(t, smem_u32(&Bs[nr * BSTR + col]));
                bf[g * 2 + 0][0] = t[0]; bf[g * 2 + 0][1] = t[1];
                bf[g * 2 + 1][0] = t[2]; bf[g * 2 + 1][1] = t[3];
            }
            #pragma unroll
            for (int mt = 0; mt < 2; ++mt)
                #pragma unroll
                for (int nt = 0; nt < 4; ++nt)
                    mma_f16(acc[mt][nt], af[mt], bf[nt]);
        }
        __syncthreads();
    }

    // epilogue
    #pragma unroll
    for (int mt = 0; mt < 2; ++mt) {
        int r0 = m0 + wm * 32 + mt * 16 + (lane >> 2);
        int r1 = r0 + 8;
        #pragma unroll
        for (int nt = 0; nt < 4; ++nt) {
            int cb = n0 + wn * 32 + nt * 8 + 2 * (lane & 3);
            float b0 = bias[cb], b1 = bias[cb + 1];
            float v0 = acc[mt][nt][0] + b0;
            float v1 = acc[mt][nt][1] + b1;
            float v2 = acc[mt][nt][2] + b0;
            float v3 = acc[mt][nt][3] + b1;
            if (RELU) {
                v0 = fmaxf(v0, 0.f); v1 = fmaxf(v1, 0.f);
                v2 = fmaxf(v2, 0.f); v3 = fmaxf(v3, 0.f);
            }
            if (HALF_OUT) {
                __half* Ch = (__half*)Cv;
                if (r0 < M)
                    *reinterpret_cast<__half2*>(&Ch[(size_t)r0 * N + cb]) = __floats2half2_rn(v0, v1);
                if (r1 < M)
                    *reinterpret_cast<__half2*>(&Ch[(size_t)r1 * N + cb]) = __floats2half2_rn(v2, v3);
            } else {
                float* Cf = (float*)Cv;
                if (r0 < M)
                    *reinterpret_cast<float2*>(&Cf[(size_t)r0 * N + cb]) = make_float2(v0, v1);
                if (r1 < M)
                    *reinterpret_cast<float2*>(&Cf[(size_t)r1 * N + cb]) = make_float2(v2, v3);
            }
        }
    }
}

// ---------------- deformable attention sampling (fp16 values) ----------------
__global__ void deform_kernel(const __half* __restrict__ pvalh, const float* __restrict__ poff,
                              const float* __restrict__ plog, const float* __restrict__ pref,
                              __half* __restrict__ psamph) {
    int gwarp = (blockIdx.x * blockDim.x + threadIdx.x) >> 5;
    int lane = threadIdx.x & 31;
    if (gwarp >= BATCH * QTOT * NH) return;
    int h = gwarp % NH;
    int q = (gwarp / NH) % QTOT;
    int b = gwarp / (NH * QTOT);
    size_t tok = (size_t)b * QTOT + q;

    const float* lrow = &plog[tok * 128 + h * 16];
    const float* orow = &poff[tok * 256 + h * 32];

    float lg[16];
    float mx = -1e30f;
    #pragma unroll
    for (int i = 0; i < 16; ++i) { lg[i] = __ldg(&lrow[i]); mx = fmaxf(mx, lg[i]); }
    float ssum = 0.f;
    #pragma unroll
    for (int i = 0; i < 16; ++i) { lg[i] = expf(lg[i] - mx); ssum += lg[i]; }
    float inv = 1.f / ssum;

    float rx = pref[2 * q];
    float ry = pref[2 * q + 1];

    float acc = 0.f;
    #pragma unroll
    for (int p = 0; p < 16; ++p) {
        int l = p >> 2;
        float w  = lg[p] * inv;
        float ox = __ldg(&orow[2 * p]);
        float oy = __ldg(&orow[2 * p + 1]);
        int Wl = c_W[l], Hl = c_H[l];
        float fw = (float)Wl, fh = (float)Hl;
        float x = (rx + ox / fw) * fw - 0.5f;
        float y = (ry + oy / fh) * fh - 0.5f;
        float x0f = floorf(x), y0f = floorf(y);
        int x0 = (int)x0f, y0 = (int)y0f;
        float fx = x - x0f, fy = y - y0f;
        size_t base = (size_t)b * QTOT + c_start[l];
        #pragma unroll
        for (int dy = 0; dy < 2; ++dy) {
            #pragma unroll
            for (int dx = 0; dx < 2; ++dx) {
                int xi = x0 + dx, yi = y0 + dy;
                if (xi >= 0 && xi < Wl && yi >= 0 && yi < Hl) {
                    float bw = (dx ? fx : 1.f - fx) * (dy ? fy : 1.f - fy);
                    float v = __half2float(pvalh[(base + (size_t)yi * Wl + xi) * DMODEL + h * HD + lane]);
                    acc = fmaf(w * bw, v, acc);
                }
            }
        }
    }
    psamph[tok * DMODEL + h * HD + lane] = __float2half_rn(acc);
}

// ---------------- fused residual + layernorm: x = LN(x + y); dual write f32+f16 ----------------
__global__ void ln_res_kernel(float* __restrict__ px, __half* __restrict__ pxh,
                              const float* __restrict__ y,
                              const float* __restrict__ g, const float* __restrict__ bb) {
    int warp = (blockIdx.x * blockDim.x + threadIdx.x) >> 5;
    int lane = threadIdx.x & 31;
    if (warp >= BQ) return;
    size_t base = (size_t)warp * DMODEL;
    float v[8];
    float s = 0.f, s2 = 0.f;
    #pragma unroll
    for (int k = 0; k < 8; ++k) {
        int d = k * 32 + lane;
        v[k] = px[base + d] + y[base + d];
        s += v[k];
        s2 += v[k] * v[k];
    }
    s = wredsum(s);
    s2 = wredsum(s2);
    float m = s * (1.f / DMODEL);
    float var = s2 * (1.f / DMODEL) - m * m;
    float rstd = rsqrtf(var + 1e-5f);
    #pragma unroll
    for (int k = 0; k < 8; ++k) {
        int d = k * 32 + lane;
        float o = (v[k] - m) * rstd * g[d] + bb[d];
        px[base + d]  = o;
        pxh[base + d] = __float2half_rn(o);
    }
}

// ---------------- copy out ----------------
__global__ void copyout_kernel(float* __restrict__ out, const float* __restrict__ px) {
    int idx = blockIdx.x * blockDim.x + threadIdx.x;
    if (idx >= BQ * DMODEL) return;
    out[idx] = px[idx];
}

// ---------------- launch ----------------
extern "C" void kernel_launch(void* const* d_in, const int* in_sizes, int n_in,
                              void* d_out, int out_size) {
    (void)n_in; (void)out_size;

    float *px, *ppos, *poff, *plog, *pattn, *pff2, *pref;
    __half *pxh, *pqh, *pvalh, *psamph, *pffh, *pwt;
    cudaGetSymbolAddress((void**)&px,    g_x);
    cudaGetSymbolAddress((void**)&ppos,  g_pos);
    cudaGetSymbolAddress((void**)&poff,  g_off);
    cudaGetSymbolAddress((void**)&plog,  g_logits);
    cudaGetSymbolAddress((void**)&pattn, g_attnout);
    cudaGetSymbolAddress((void**)&pff2,  g_ff2);
    cudaGetSymbolAddress((void**)&pref,  g_ref);
    cudaGetSymbolAddress((void**)&pxh,   g_xh);
    cudaGetSymbolAddress((void**)&pqh,   g_qh);
    cudaGetSymbolAddress((void**)&pvalh, g_valh);
    cudaGetSymbolAddress((void**)&psamph,g_samph);
    cudaGetSymbolAddress((void**)&pffh,  g_ffh);
    cudaGetSymbolAddress((void**)&pwt,   g_wt);

    bool interleaved = (in_sizes[1] == in_sizes[0]);
    const float* src[4];
    const float* pos[4];
    for (int i = 0; i < 4; ++i) {
        if (interleaved) {
            src[i] = (const float*)d_in[2 * i];
            pos[i] = (const float*)d_in[2 * i + 1];
        } else {
            src[i] = (const float*)d_in[i];
            pos[i] = (const float*)d_in[4 + i];
        }
    }
    const float* level_embed = (const float*)d_in[8];
    const float* Woff  = (const float*)d_in[9];
    const float* boff  = (const float*)d_in[10];
    const float* Wattn = (const float*)d_in[11];
    const float* battn = (const float*)d_in[12];
    const float* Wv    = (const float*)d_in[13];
    const float* bv    = (const float*)d_in[14];
    const float* Wo    = (const float*)d_in[15];
    const float* bo    = (const float*)d_in[16];
    const float* g1    = (const float*)d_in[17];
    const float* b1    = (const float*)d_in[18];
    const float* W1    = (const float*)d_in[19];
    const float* bb1   = (const float*)d_in[20];
    const float* W2    = (const float*)d_in[21];
    const float* bb2   = (const float*)d_in[22];
    const float* g2    = (const float*)d_in[23];
    const float* b2    = (const float*)d_in[24];
    float* out = (float*)d_out;

    const int hws[4]    = {10000, 2500, 625, 169};
    const int starts[4] = {0, 10000, 12500, 13125};

    for (int l = 0; l < 4; ++l) {
        int total = BATCH * hws[l] * DMODEL;
        flatten_kernel<<<(total + 255) / 256, 256>>>(px, pxh, ppos, src[l], pos[l],
                                                     level_embed + l * DMODEL, starts[l], hws[l]);
    }
    ref_kernel<<<(QTOT + 255) / 256, 256>>>(pref);

    const int OFF_WOFF = 0;
    const int OFF_WATTN = 65536;
    const int OFF_WV = 98304;
    const int OFF_WO = 163840;
    const int OFF_W1 = 229376;
    const int OFF_W2 = 491520;

    for (int l = 0; l < NLAYERS; ++l) {
        __half* wt = pwt + (size_t)l * WT_LAYER;
        transpose_kernel<<<(65536 + 255) / 256, 256>>>(wt + OFF_WOFF,  Woff  + (size_t)l * 65536, 256, 256);
        transpose_kernel<<<(32768 + 255) / 256, 256>>>(wt + OFF_WATTN, Wattn + (size_t)l * 32768, 256, 128);
        transpose_kernel<<<(65536 + 255) / 256, 256>>>(wt + OFF_WV,    Wv    + (size_t)l * 65536, 256, 256);
        transpose_kernel<<<(65536 + 255) / 256, 256>>>(wt + OFF_WO,    Wo    + (size_t)l * 65536, 256, 256);
        transpose_kernel<<<(262144 + 255) / 256, 256>>>(wt + OFF_W1,   W1    + (size_t)l * 262144, 256, 1024);
        transpose_kernel<<<(262144 + 255) / 256, 256>>>(wt + OFF_W2,   W2    + (size_t)l * 262144, 1024, 256);
    }

    const int ew_grid = (BQ * DMODEL + 255) / 256;
    const int mblocks = (BQ + TM - 1) / TM;                    // 208
    const int warp_grid_deform = (BATCH * QTOT * NH + 7) / 8;
    const int warp_grid_ln = (BQ + 7) / 8;

    for (int l = 0; l < NLAYERS; ++l) {
        __half* wt = pwt + (size_t)l * WT_LAYER;
        const float* boff_l  = boff  + (size_t)l * 256;
        const float* battn_l = battn + (size_t)l * 128;
        const float* bv_l    = bv    + (size_t)l * DMODEL;
        const float* bo_l    = bo    + (size_t)l * DMODEL;
        const float* bb1_l   = bb1   + (size_t)l * DFF;
        const float* bb2_l   = bb2   + (size_t)l * DMODEL;

        addq_kernel<<<ew_grid, 256>>>(pqh, px, ppos);

        gemm_h_kernel<false, false><<<dim3(mblocks, 256 / TN), 256>>>(
            pqh, wt + OFF_WOFF, boff_l, poff, BQ, 256, 256);
        gemm_h_kernel<false, false><<<dim3(mblocks, 128 / TN), 256>>>(
            pqh, wt + OFF_WATTN, battn_l, plog, BQ, 128, 256);
        gemm_h_kernel<false, true><<<dim3(mblocks, 256 / TN), 256>>>(
            pxh, wt + OFF_WV, bv_l, pvalh, BQ, 256, 256);

        deform_kernel<<<warp_grid_deform, 256>>>(pvalh, poff, plog, pref, psamph);

        gemm_h_kernel<false, false><<<dim3(mblocks, 256 / TN), 256>>>(
            psamph, wt + OFF_WO, bo_l, pattn, BQ, 256, 256);

        ln_res_kernel<<<warp_grid_ln, 256>>>(px, pxh, pattn,
                                             g1 + (size_t)l * DMODEL, b1 + (size_t)l * DMODEL);

        gemm_h_kernel<true, true><<<dim3(mblocks, DFF / TN), 256>>>(
            pxh, wt + OFF_W1, bb1_l, pffh, BQ, DFF, 256);
        gemm_h_kernel<false, false><<<dim3(mblocks, 256 / TN), 256>>>(
            pffh, wt + OFF_W2, bb2_l, pff2, BQ, 256, 1024);

        ln_res_kernel<<<warp_grid_ln, 256>>>(px, pxh, pff2,
                                             g2 + (size_t)l * DMODEL, b2 + (size_t)l * DMODEL);
    }

    copyout_kernel<<<ew_grid, 256>>>(out, px);
}

// round 9
// speedup vs baseline: 2.0850x; 1.0200x over previous
#include <cuda_runtime.h>
#include <cuda_fp16.h>
#include <cstdint>

// ---------------- problem constants ----------------
#define QTOT   13294
#define BATCH  2
#define BQ     (BATCH*QTOT)   // 26588
#define DMODEL 256
#define NH     8
#define HD     32
#define DFF    1024
#define NLAYERS 6

__constant__ int c_start[4] = {0, 10000, 12500, 13125};
__constant__ int c_H[4]     = {100, 50, 25, 13};
__constant__ int c_W[4]     = {100, 50, 25, 13};

// ---------------- device scratch ----------------
__device__ float  g_x[BQ * DMODEL];         // fp32 residual stream
__device__ float  g_pos[BQ * DMODEL];
__device__ float  g_offlog[BQ * 384];       // [0,256)=offsets, [256,384)=logits
__device__ float  g_attnout[BQ * DMODEL];
__device__ float  g_ff2[BQ * DMODEL];
__device__ float  g_ref[QTOT * 2];
__device__ float  g_bcomb[NLAYERS * 384];   // combined boff|battn
__device__ __half g_xh[BQ * DMODEL];
__device__ __half g_valh[BQ * DMODEL];
__device__ __half g_samph[BQ * DMODEL];
__device__ __half g_ffh[BQ * DFF];
// packed transposed fp16 weights per layer:
// WoaT(384x256)=98304, WvT=65536, WoT=65536, W1T(1024x256)=262144, W2T(256x1024)=262144
#define WT_LAYER 753664
#define OFF_WOA 0
#define OFF_WV  98304
#define OFF_WO  163840
#define OFF_W1  229376
#define OFF_W2  491520
__device__ __half g_wt[NLAYERS * WT_LAYER];

// ---------------- helpers ----------------
__device__ __forceinline__ float wredsum(float v) {
    #pragma unroll
    for (int o = 16; o; o >>= 1) v += __shfl_xor_sync(0xffffffffu, v, o);
    return v;
}
__device__ __forceinline__ uint32_t smem_u32(const void* p) {
    uint32_t a;
    asm("{ .reg .u64 t; cvta.to.shared.u64 t, %1; cvt.u32.u64 %0, t; }" : "=r"(a) : "l"(p));
    return a;
}
#define LDSM4(r, addr) \
    asm volatile("ldmatrix.sync.aligned.m8n8.x4.shared.b16 {%0,%1,%2,%3}, [%4];" \
        : "=r"((r)[0]), "=r"((r)[1]), "=r"((r)[2]), "=r"((r)[3]) : "r"(addr))

__device__ __forceinline__ void mma_f16(float* c, const uint32_t* a, const uint32_t* b) {
    asm volatile(
        "mma.sync.aligned.m16n8k16.row.col.f32.f16.f16.f32 "
        "{%0,%1,%2,%3}, {%4,%5,%6,%7}, {%8,%9}, {%0,%1,%2,%3};"
        : "+f"(c[0]), "+f"(c[1]), "+f"(c[2]), "+f"(c[3])
        : "r"(a[0]), "r"(a[1]), "r"(a[2]), "r"(a[3]), "r"(b[0]), "r"(b[1]));
}
__device__ __forceinline__ uint32_t packh2(float a, float b) {
    __half2 h = __floats2half2_rn(a, b);
    return *reinterpret_cast<uint32_t*>(&h);
}

// ---------------- flatten ----------------
__global__ void flatten_kernel(float* __restrict__ px, __half* __restrict__ pxh,
                               float* __restrict__ ppos,
                               const float* __restrict__ src, const float* __restrict__ pos,
                               const float* __restrict__ le, int start, int hw) {
    int idx = blockIdx.x * blockDim.x + threadIdx.x;
    int total = BATCH * hw * DMODEL;
    if (idx >= total) return;
    int d = idx & 255;
    int p = (idx >> 8) % hw;
    int b = idx / (DMODEL * hw);
    size_t sidx = ((size_t)b * DMODEL + d) * hw + p;
    size_t tok  = (size_t)b * QTOT + start + p;
    float v = src[sidx];
    px[tok * DMODEL + d]  = v;
    pxh[tok * DMODEL + d] = __float2half_rn(v);
    ppos[tok * DMODEL + d] = pos[sidx] + le[d];
}

// ---------------- reference points ----------------
__global__ void ref_kernel(float* __restrict__ pref) {
    int q = blockIdx.x * blockDim.x + threadIdx.x;
    if (q >= QTOT) return;
    int l = 3;
    if (q < 10000) l = 0; else if (q < 12500) l = 1; else if (q < 13125) l = 2;
    int loc = q - c_start[l];
    int W = c_W[l];
    int yy = loc / W, xx = loc - yy * W;
    pref[2 * q]     = (xx + 0.5f) / (float)c_W[l];
    pref[2 * q + 1] = (yy + 0.5f) / (float)c_H[l];
}

// ---------------- weight packing (all layers in one launch each) ----------------
__global__ void transpose_woa(__half* __restrict__ pwt,
                              const float* __restrict__ woff, const float* __restrict__ wattn) {
    int idx = blockIdx.x * blockDim.x + threadIdx.x;
    int total = NLAYERS * 384 * 256;
    if (idx >= total) return;
    int l = idx / (384 * 256);
    int rem = idx - l * 384 * 256;
    int n = rem >> 8, k = rem & 255;
    float v = (n < 256) ? woff[(size_t)l * 65536 + k * 256 + n]
                        : wattn[(size_t)l * 32768 + k * 128 + (n - 256)];
    pwt[(size_t)l * WT_LAYER + OFF_WOA + n * 256 + k] = __float2half_rn(v);
}
__global__ void transpose_nl(__half* __restrict__ out, const float* __restrict__ in,
                             int K, int N) {
    int idx = blockIdx.x * blockDim.x + threadIdx.x;
    int total = NLAYERS * N * K;
    if (idx >= total) return;
    int l = idx / (N * K);
    int rem = idx - l * N * K;
    int n = rem / K, k = rem - n * K;
    out[(size_t)l * WT_LAYER + n * K + k] = __float2half_rn(in[(size_t)l * K * N + k * N + n]);
}
__global__ void bias_comb_kernel(float* __restrict__ out, const float* __restrict__ boff,
                                 const float* __restrict__ battn) {
    int idx = blockIdx.x * blockDim.x + threadIdx.x;
    if (idx >= NLAYERS * 384) return;
    int l = idx / 384, j = idx - l * 384;
    out[idx] = (j < 384 && j < 256) ? boff[l * 256 + j] : battn[l * 128 + (j - 256)];
}

// ---------------- fp16 mma.sync GEMM ----------------
// block 128x64, 8 warps (4M x 2N), warp tile 32x32, mma m16n8k16, KC=32,
// reg-double-buffered staging, ldmatrix fragments, padded stride 40 halves.
// FUSE: A = half(A1f + A2f) computed during staging (fp32 sources).
#define TM 128
#define TN 64
#define ASTR 40
#define BSTR 40

template<bool RELU, bool HALF_OUT, bool FUSE>
__global__ void __launch_bounds__(256) gemm_h_kernel(
    const void* __restrict__ Av, const float* __restrict__ A2,
    const __half* __restrict__ Bt,
    const float* __restrict__ bias, void* __restrict__ Cv,
    int M, int N, int K)
{
    __shared__ __align__(16) __half smA[2][TM * ASTR];
    __shared__ __align__(16) __half smB[2][TN * BSTR];

    int tid = threadIdx.x;
    int wid = tid >> 5, lane = tid & 31;
    int wm = wid & 3, wn = wid >> 2;
    int m0 = blockIdx.x * TM;
    int n0 = blockIdx.y * TN;
    int NC = K >> 5;

    int arow = tid >> 1, ahalf = tid & 1;   // A: 2 thr/row, 16 halves each
    int brow = tid >> 2, bq = tid & 3;      // B: 4 thr/row, 8 halves each
    int aRowG = m0 + arow;
    int aRowC = (aRowG < M) ? aRowG : (M - 1);

    float acc[2][4][4];
    #pragma unroll
    for (int i = 0; i < 2; ++i)
        #pragma unroll
        for (int j = 0; j < 4; ++j)
            #pragma unroll
            for (int r = 0; r < 4; ++r) acc[i][j][r] = 0.f;

    uint4 ra0, ra1, rb;
    // preload chunk 0
    if (FUSE) {
        const float* x = (const float*)Av + (size_t)aRowC * K + ahalf * 16;
        const float* p = A2 + (size_t)aRowC * K + ahalf * 16;
        float4 x0 = *(const float4*)(x), x1 = *(const float4*)(x + 4);
        float4 x2 = *(const float4*)(x + 8), x3 = *(const float4*)(x + 12);
        float4 p0 = *(const float4*)(p), p1 = *(const float4*)(p + 4);
        float4 p2 = *(const float4*)(p + 8), p3 = *(const float4*)(p + 12);
        ra0.x = packh2(x0.x + p0.x, x0.y + p0.y); ra0.y = packh2(x0.z + p0.z, x0.w + p0.w);
        ra0.z = packh2(x1.x + p1.x, x1.y + p1.y); ra0.w = packh2(x1.z + p1.z, x1.w + p1.w);
        ra1.x = packh2(x2.x + p2.x, x2.y + p2.y); ra1.y = packh2(x2.z + p2.z, x2.w + p2.w);
        ra1.z = packh2(x3.x + p3.x, x3.y + p3.y); ra1.w = packh2(x3.z + p3.z, x3.w + p3.w);
    } else {
        const uint4* aG = (const uint4*)((const __half*)Av + (size_t)aRowC * K + ahalf * 16);
        ra0 = aG[0]; ra1 = aG[1];
    }
    rb = *(const uint4*)&Bt[(size_t)(n0 + brow) * K + bq * 8];

    int sub = lane >> 3, lrow = lane & 7;

    for (int c = 0; c < NC; ++c) {
        int buf = c & 1;
        *reinterpret_cast<uint4*>(&smA[buf][arow * ASTR + ahalf * 16])     = ra0;
        *reinterpret_cast<uint4*>(&smA[buf][arow * ASTR + ahalf * 16 + 8]) = ra1;
        *reinterpret_cast<uint4*>(&smB[buf][brow * BSTR + bq * 8])         = rb;
        if (c + 1 < NC) {
            int ko = (c + 1) * 32 + ahalf * 16;
            if (FUSE) {
                const float* x = (const float*)Av + (size_t)aRowC * K + ko;
                const float* p = A2 + (size_t)aRowC * K + ko;
                float4 x0 = *(const float4*)(x), x1 = *(const float4*)(x + 4);
                float4 x2 = *(const float4*)(x + 8), x3 = *(const float4*)(x + 12);
                float4 p0 = *(const float4*)(p), p1 = *(const float4*)(p + 4);
                float4 p2 = *(const float4*)(p + 8), p3 = *(const float4*)(p + 12);
                ra0.x = packh2(x0.x + p0.x, x0.y + p0.y); ra0.y = packh2(x0.z + p0.z, x0.w + p0.w);
                ra0.z = packh2(x1.x + p1.x, x1.y + p1.y); ra0.w = packh2(x1.z + p1.z, x1.w + p1.w);
                ra1.x = packh2(x2.x + p2.x, x2.y + p2.y); ra1.y = packh2(x2.z + p2.z, x2.w + p2.w);
                ra1.z = packh2(x3.x + p3.x, x3.y + p3.y); ra1.w = packh2(x3.z + p3.z, x3.w + p3.w);
            } else {
                const uint4* aGn = (const uint4*)((const __half*)Av + (size_t)aRowC * K + ko);
                ra0 = aGn[0]; ra1 = aGn[1];
            }
            rb = *(const uint4*)&Bt[(size_t)(n0 + brow) * K + (c + 1) * 32 + bq * 8];
        }
        __syncthreads();

        const __half* As = smA[buf];
        const __half* Bs = smB[buf];
        #pragma unroll
        for (int ks = 0; ks < 2; ++ks) {
            uint32_t af[2][4];
            #pragma unroll
            for (int mt = 0; mt < 2; ++mt) {
                int r = wm * 32 + mt * 16 + ((sub & 1) << 3) + lrow;
                int col = ks * 16 + ((sub >> 1) << 3);
                LDSM4(af[mt], smem_u32(&As[r * ASTR + col]));
            }
            uint32_t bf[4][2];
            #pragma unroll
            for (int g = 0; g < 2; ++g) {
                int nr = wn * 32 + ((g * 2 + (sub >> 1)) << 3) + lrow;
                int col = ks * 16 + ((sub & 1) << 3);
                uint32_t t[4];
                LDSM4(t, smem_u32(&Bs[nr * BSTR + col]));
                bf[g * 2 + 0][0] = t[0]; bf[g * 2 + 0][1] = t[1];
                bf[g * 2 + 1][0] = t[2]; bf[g * 2 + 1][1] = t[3];
            }
            #pragma unroll
            for (int mt = 0; mt < 2; ++mt)
                #pragma unroll
                for (int nt = 0; nt < 4; ++nt)
                    mma_f16(acc[mt][nt], af[mt], bf[nt]);
        }
        __syncthreads();
    }

    #pragma unroll
    for (int mt = 0; mt < 2; ++mt) {
        int r0 = m0 + wm * 32 + mt * 16 + (lane >> 2);
        int r1 = r0 + 8;
        #pragma unroll
        for (int nt = 0; nt < 4; ++nt) {
            int cb = n0 + wn * 32 + nt * 8 + 2 * (lane & 3);
            float b0 = bias[cb], b1 = bias[cb + 1];
            float v0 = acc[mt][nt][0] + b0;
            float v1 = acc[mt][nt][1] + b1;
            float v2 = acc[mt][nt][2] + b0;
            float v3 = acc[mt][nt][3] + b1;
            if (RELU) {
                v0 = fmaxf(v0, 0.f); v1 = fmaxf(v1, 0.f);
                v2 = fmaxf(v2, 0.f); v3 = fmaxf(v3, 0.f);
            }
            if (HALF_OUT) {
                __half* Ch = (__half*)Cv;
                if (r0 < M)
                    *reinterpret_cast<__half2*>(&Ch[(size_t)r0 * N + cb]) = __floats2half2_rn(v0, v1);
                if (r1 < M)
                    *reinterpret_cast<__half2*>(&Ch[(size_t)r1 * N + cb]) = __floats2half2_rn(v2, v3);
            } else {
                float* Cf = (float*)Cv;
                if (r0 < M)
                    *reinterpret_cast<float2*>(&Cf[(size_t)r0 * N + cb]) = make_float2(v0, v1);
                if (r1 < M)
                    *reinterpret_cast<float2*>(&Cf[(size_t)r1 * N + cb]) = make_float2(v2, v3);
            }
        }
    }
}

// ---------------- deformable attention sampling ----------------
__global__ void deform_kernel(const __half* __restrict__ pvalh, const float* __restrict__ pol,
                              const float* __restrict__ pref, __half* __restrict__ psamph) {
    int gwarp = (blockIdx.x * blockDim.x + threadIdx.x) >> 5;
    int lane = threadIdx.x & 31;
    if (gwarp >= BATCH * QTOT * NH) return;
    int h = gwarp % NH;
    int q = (gwarp / NH) % QTOT;
    int b = gwarp / (NH * QTOT);
    size_t tok = (size_t)b * QTOT + q;

    const float* orow = &pol[tok * 384 + h * 32];         // 16 (x,y) pairs
    const float* lrow = &pol[tok * 384 + 256 + h * 16];   // 16 logits

    float lg[16];
    float mx = -1e30f;
    #pragma unroll
    for (int i = 0; i < 16; ++i) { lg[i] = __ldg(&lrow[i]); mx = fmaxf(mx, lg[i]); }
    float ssum = 0.f;
    #pragma unroll
    for (int i = 0; i < 16; ++i) { lg[i] = expf(lg[i] - mx); ssum += lg[i]; }
    float inv = 1.f / ssum;

    float rx = pref[2 * q];
    float ry = pref[2 * q + 1];

    float acc = 0.f;
    #pragma unroll
    for (int p = 0; p < 16; ++p) {
        int l = p >> 2;
        float w  = lg[p] * inv;
        float ox = __ldg(&orow[2 * p]);
        float oy = __ldg(&orow[2 * p + 1]);
        int Wl = c_W[l], Hl = c_H[l];
        float fw = (float)Wl, fh = (float)Hl;
        float x = (rx + ox / fw) * fw - 0.5f;
        float y = (ry + oy / fh) * fh - 0.5f;
        float x0f = floorf(x), y0f = floorf(y);
        int x0 = (int)x0f, y0 = (int)y0f;
        float fx = x - x0f, fy = y - y0f;
        size_t base = (size_t)b * QTOT + c_start[l];
        #pragma unroll
        for (int dy = 0; dy < 2; ++dy) {
            #pragma unroll
            for (int dx = 0; dx < 2; ++dx) {
                int xi = x0 + dx, yi = y0 + dy;
                if (xi >= 0 && xi < Wl && yi >= 0 && yi < Hl) {
                    float bw = (dx ? fx : 1.f - fx) * (dy ? fy : 1.f - fy);
                    float v = __half2float(pvalh[(base + (size_t)yi * Wl + xi) * DMODEL + h * HD + lane]);
                    acc = fmaf(w * bw, v, acc);
                }
            }
        }
    }
    psamph[tok * DMODEL + h * HD + lane] = __float2half_rn(acc);
}

// ---------------- fused residual + layernorm (optional direct out write) ----------------
__global__ void ln_res_kernel(float* __restrict__ px, __half* __restrict__ pxh,
                              const float* __restrict__ y,
                              const float* __restrict__ g, const float* __restrict__ bb,
                              float* __restrict__ outp) {
    int warp = (blockIdx.x * blockDim.x + threadIdx.x) >> 5;
    int lane = threadIdx.x & 31;
    if (warp >= BQ) return;
    size_t base = (size_t)warp * DMODEL;
    float v[8];
    float s = 0.f, s2 = 0.f;
    #pragma unroll
    for (int k = 0; k < 8; ++k) {
        int d = k * 32 + lane;
        v[k] = px[base + d] + y[base + d];
        s += v[k];
        s2 += v[k] * v[k];
    }
    s = wredsum(s);
    s2 = wredsum(s2);
    float m = s * (1.f / DMODEL);
    float var = s2 * (1.f / DMODEL) - m * m;
    float rstd = rsqrtf(var + 1e-5f);
    #pragma unroll
    for (int k = 0; k < 8; ++k) {
        int d = k * 32 + lane;
        float o = (v[k] - m) * rstd * g[d] + bb[d];
        px[base + d]  = o;
        pxh[base + d] = __float2half_rn(o);
        if (outp) outp[base + d] = o;
    }
}

// ---------------- launch ----------------
extern "C" void kernel_launch(void* const* d_in, const int* in_sizes, int n_in,
                              void* d_out, int out_size) {
    (void)n_in; (void)out_size;

    float *px, *ppos, *pol, *pattn, *pff2, *pref, *pbc;
    __half *pxh, *pvalh, *psamph, *pffh, *pwt;
    cudaGetSymbolAddress((void**)&px,    g_x);
    cudaGetSymbolAddress((void**)&ppos,  g_pos);
    cudaGetSymbolAddress((void**)&pol,   g_offlog);
    cudaGetSymbolAddress((void**)&pattn, g_attnout);
    cudaGetSymbolAddress((void**)&pff2,  g_ff2);
    cudaGetSymbolAddress((void**)&pref,  g_ref);
    cudaGetSymbolAddress((void**)&pbc,   g_bcomb);
    cudaGetSymbolAddress((void**)&pxh,   g_xh);
    cudaGetSymbolAddress((void**)&pvalh, g_valh);
    cudaGetSymbolAddress((void**)&psamph,g_samph);
    cudaGetSymbolAddress((void**)&pffh,  g_ffh);
    cudaGetSymbolAddress((void**)&pwt,   g_wt);

    bool interleaved = (in_sizes[1] == in_sizes[0]);
    const float* src[4];
    const float* pos[4];
    for (int i = 0; i < 4; ++i) {
        if (interleaved) {
            src[i] = (const float*)d_in[2 * i];
            pos[i] = (const float*)d_in[2 * i + 1];
        } else {
            src[i] = (const float*)d_in[i];
            pos[i] = (const float*)d_in[4 + i];
        }
    }
    const float* level_embed = (const float*)d_in[8];
    const float* Woff  = (const float*)d_in[9];
    const float* boff  = (const float*)d_in[10];
    const float* Wattn = (const float*)d_in[11];
    const float* battn = (const float*)d_in[12];
    const float* Wv    = (const float*)d_in[13];
    const float* bv    = (const float*)d_in[14];
    const float* Wo    = (const float*)d_in[15];
    const float* bo    = (const float*)d_in[16];
    const float* g1    = (const float*)d_in[17];
    const float* b1    = (const float*)d_in[18];
    const float* W1    = (const float*)d_in[19];
    const float* bb1   = (const float*)d_in[20];
    const float* W2    = (const float*)d_in[21];
    const float* bb2   = (const float*)d_in[22];
    const float* g2    = (const float*)d_in[23];
    const float* b2    = (const float*)d_in[24];
    float* out = (float*)d_out;

    const int hws[4]    = {10000, 2500, 625, 169};
    const int starts[4] = {0, 10000, 12500, 13125};

    for (int l = 0; l < 4; ++l) {
        int total = BATCH * hws[l] * DMODEL;
        flatten_kernel<<<(total + 255) / 256, 256>>>(px, pxh, ppos, src[l], pos[l],
                                                     level_embed + l * DMODEL, starts[l], hws[l]);
    }
    ref_kernel<<<(QTOT + 255) / 256, 256>>>(pref);

    // weight packing: 6 launches total
    transpose_woa<<<(NLAYERS * 384 * 256 + 255) / 256, 256>>>(pwt, Woff, Wattn);
    transpose_nl<<<(NLAYERS * 256 * 256 + 255) / 256, 256>>>(pwt + OFF_WV, Wv, 256, 256);
    transpose_nl<<<(NLAYERS * 256 * 256 + 255) / 256, 256>>>(pwt + OFF_WO, Wo, 256, 256);
    transpose_nl<<<(NLAYERS * 1024 * 256 + 255) / 256, 256>>>(pwt + OFF_W1, W1, 256, 1024);
    transpose_nl<<<(NLAYERS * 256 * 1024 + 255) / 256, 256>>>(pwt + OFF_W2, W2, 1024, 256);
    bias_comb_kernel<<<(NLAYERS * 384 + 255) / 256, 256>>>(pbc, boff, battn);

    const int mblocks = (BQ + TM - 1) / TM;                    // 208
    const int warp_grid_deform = (BATCH * QTOT * NH + 7) / 8;
    const int warp_grid_ln = (BQ + 7) / 8;

    for (int l = 0; l < NLAYERS; ++l) {
        __half* wt = pwt + (size_t)l * WT_LAYER;
        const float* bcomb_l = pbc + (size_t)l * 384;
        const float* bv_l    = bv  + (size_t)l * DMODEL;
        const float* bo_l    = bo  + (size_t)l * DMODEL;
        const float* bb1_l   = bb1 + (size_t)l * DFF;
        const float* bb2_l   = bb2 + (size_t)l * DMODEL;

        // fused (x+pos) -> [offsets | logits], N=384
        gemm_h_kernel<false, false, true><<<dim3(mblocks, 384 / TN), 256>>>(
            px, ppos, wt + OFF_WOA, bcomb_l, pol, BQ, 384, 256);
        // values
        gemm_h_kernel<false, true, false><<<dim3(mblocks, 256 / TN), 256>>>(
            pxh, nullptr, wt + OFF_WV, bv_l, pvalh, BQ, 256, 256);

        deform_kernel<<<warp_grid_deform, 256>>>(pvalh, pol, pref, psamph);

        gemm_h_kernel<false, false, false><<<dim3(mblocks, 256 / TN), 256>>>(
            psamph, nullptr, wt + OFF_WO, bo_l, pattn, BQ, 256, 256);

        ln_res_kernel<<<warp_grid_ln, 256>>>(px, pxh, pattn,
                                             g1 + (size_t)l * DMODEL, b1 + (size_t)l * DMODEL,
                                             nullptr);

        gemm_h_kernel<true, true, false><<<dim3(mblocks, DFF / TN), 256>>>(
            pxh, nullptr, wt + OFF_W1, bb1_l, pffh, BQ, DFF, 256);
        gemm_h_kernel<false, false, false><<<dim3(mblocks, 256 / TN), 256>>>(
            pffh, nullptr, wt + OFF_W2, bb2_l, pff2, BQ, 256, 1024);

        ln_res_kernel<<<warp_grid_ln, 256>>>(px, pxh, pff2,
                                             g2 + (size_t)l * DMODEL, b2 + (size_t)l * DMODEL,
                                             (l == NLAYERS - 1) ? out : nullptr);
    }
}

// round 10
// speedup vs baseline: 2.3014x; 1.1038x over previous
#include <cuda_runtime.h>
#include <cuda_fp16.h>
#include <cstdint>

// ---------------- problem constants ----------------
#define QTOT   13294
#define BATCH  2
#define BQ     (BATCH*QTOT)   // 26588
#define DMODEL 256
#define NH     8
#define HD     32
#define DFF    1024
#define NLAYERS 6

__constant__ int c_start[4] = {0, 10000, 12500, 13125};
__constant__ int c_H[4]     = {100, 50, 25, 13};
__constant__ int c_W[4]     = {100, 50, 25, 13};

// ---------------- device scratch ----------------
__device__ float  g_x[BQ * DMODEL];
__device__ float  g_pos[BQ * DMODEL];
__device__ float  g_offlog[BQ * 384];
__device__ float  g_attnout[BQ * DMODEL];
__device__ float  g_ff2[BQ * DMODEL];
__device__ float  g_ref[QTOT * 2];
__device__ float  g_bcomb[NLAYERS * 384];
__device__ __half g_xh[BQ * DMODEL];
__device__ __half g_valh[BQ * DMODEL];
__device__ __half g_samph[BQ * DMODEL];
__device__ __half g_ffh[BQ * DFF];
#define WT_LAYER 753664
#define OFF_WOA 0
#define OFF_WV  98304
#define OFF_WO  163840
#define OFF_W1  229376
#define OFF_W2  491520
__device__ __half g_wt[NLAYERS * WT_LAYER];

// ---------------- helpers ----------------
__device__ __forceinline__ float wredsum(float v) {
    #pragma unroll
    for (int o = 16; o; o >>= 1) v += __shfl_xor_sync(0xffffffffu, v, o);
    return v;
}
__device__ __forceinline__ uint32_t smem_u32(const void* p) {
    uint32_t a;
    asm("{ .reg .u64 t; cvta.to.shared.u64 t, %1; cvt.u32.u64 %0, t; }" : "=r"(a) : "l"(p));
    return a;
}
#define LDSM4(r, addr) \
    asm volatile("ldmatrix.sync.aligned.m8n8.x4.shared.b16 {%0,%1,%2,%3}, [%4];" \
        : "=r"((r)[0]), "=r"((r)[1]), "=r"((r)[2]), "=r"((r)[3]) : "r"(addr))

__device__ __forceinline__ void mma_f16(float* c, const uint32_t* a, const uint32_t* b) {
    asm volatile(
        "mma.sync.aligned.m16n8k16.row.col.f32.f16.f16.f32 "
        "{%0,%1,%2,%3}, {%4,%5,%6,%7}, {%8,%9}, {%0,%1,%2,%3};"
        : "+f"(c[0]), "+f"(c[1]), "+f"(c[2]), "+f"(c[3])
        : "r"(a[0]), "r"(a[1]), "r"(a[2]), "r"(a[3]), "r"(b[0]), "r"(b[1]));
}
__device__ __forceinline__ uint32_t packh2(float a, float b) {
    __half2 h = __floats2half2_rn(a, b);
    return *reinterpret_cast<uint32_t*>(&h);
}
__device__ __forceinline__ void cpasync16(uint32_t dst, const void* src) {
    asm volatile("cp.async.cg.shared.global [%0], [%1], 16;"
                 :: "r"(dst), "l"(src) : "memory");
}
#define CP_COMMIT() asm volatile("cp.async.commit_group;" ::: "memory")
#define CP_WAIT0()  asm volatile("cp.async.wait_group 0;" ::: "memory")
#define CP_WAIT1()  asm volatile("cp.async.wait_group 1;" ::: "memory")

// ---------------- flatten ----------------
__global__ void flatten_kernel(float* __restrict__ px, __half* __restrict__ pxh,
                               float* __restrict__ ppos,
                               const float* __restrict__ src, const float* __restrict__ pos,
                               const float* __restrict__ le, int start, int hw) {
    int idx = blockIdx.x * blockDim.x + threadIdx.x;
    int total = BATCH * hw * DMODEL;
    if (idx >= total) return;
    int d = idx & 255;
    int p = (idx >> 8) % hw;
    int b = idx / (DMODEL * hw);
    size_t sidx = ((size_t)b * DMODEL + d) * hw + p;
    size_t tok  = (size_t)b * QTOT + start + p;
    float v = src[sidx];
    px[tok * DMODEL + d]  = v;
    pxh[tok * DMODEL + d] = __float2half_rn(v);
    ppos[tok * DMODEL + d] = pos[sidx] + le[d];
}

// ---------------- reference points ----------------
__global__ void ref_kernel(float* __restrict__ pref) {
    int q = blockIdx.x * blockDim.x + threadIdx.x;
    if (q >= QTOT) return;
    int l = 3;
    if (q < 10000) l = 0; else if (q < 12500) l = 1; else if (q < 13125) l = 2;
    int loc = q - c_start[l];
    int W = c_W[l];
    int yy = loc / W, xx = loc - yy * W;
    pref[2 * q]     = (xx + 0.5f) / (float)c_W[l];
    pref[2 * q + 1] = (yy + 0.5f) / (float)c_H[l];
}

// ---------------- weight packing ----------------
__global__ void transpose_woa(__half* __restrict__ pwt,
                              const float* __restrict__ woff, const float* __restrict__ wattn) {
    int idx = blockIdx.x * blockDim.x + threadIdx.x;
    int total = NLAYERS * 384 * 256;
    if (idx >= total) return;
    int l = idx / (384 * 256);
    int rem = idx - l * 384 * 256;
    int n = rem >> 8, k = rem & 255;
    float v = (n < 256) ? woff[(size_t)l * 65536 + k * 256 + n]
                        : wattn[(size_t)l * 32768 + k * 128 + (n - 256)];
    pwt[(size_t)l * WT_LAYER + OFF_WOA + n * 256 + k] = __float2half_rn(v);
}
__global__ void transpose_nl(__half* __restrict__ out, const float* __restrict__ in,
                             int K, int N) {
    int idx = blockIdx.x * blockDim.x + threadIdx.x;
    int total = NLAYERS * N * K;
    if (idx >= total) return;
    int l = idx / (N * K);
    int rem = idx - l * N * K;
    int n = rem / K, k = rem - n * K;
    out[(size_t)l * WT_LAYER + n * K + k] = __float2half_rn(in[(size_t)l * K * N + k * N + n]);
}
__global__ void bias_comb_kernel(float* __restrict__ out, const float* __restrict__ boff,
                                 const float* __restrict__ battn) {
    int idx = blockIdx.x * blockDim.x + threadIdx.x;
    if (idx >= NLAYERS * 384) return;
    int l = idx / 384, j = idx - l * 384;
    out[idx] = (j < 256) ? boff[l * 256 + j] : battn[l * 128 + (j - 256)];
}

// ---------------- fp16 mma.sync GEMM ----------------
// block 128x128, 8 warps (2M x 4N), warp tile 64x32, mma m16n8k16, KC=32,
// cp.async 2-stage pipeline (register staging for FUSE), stride 40 halves.
#define TM 128
#define TN 128
#define ASTR 40
#define BSTR 40

template<bool RELU, bool HALF_OUT, bool FUSE>
__global__ void __launch_bounds__(256) gemm_h_kernel(
    const void* __restrict__ Av, const float* __restrict__ A2,
    const __half* __restrict__ Bt,
    const float* __restrict__ bias, void* __restrict__ Cv,
    int M, int N, int K)
{
    __shared__ __align__(16) __half smA[2][TM * ASTR];
    __shared__ __align__(16) __half smB[2][TN * BSTR];

    int tid = threadIdx.x;
    int wid = tid >> 5, lane = tid & 31;
    int wm = wid & 1, wn = wid >> 1;          // 2 M-warps x 4 N-warps
    int m0 = blockIdx.x * TM;
    int n0 = blockIdx.y * TN;
    int NC = K >> 5;

    // staging: rows 0..127, 2 thr/row, 16 halves (32B) each
    int arow = tid >> 1, ahalf = tid & 1;
    int aRowG = m0 + arow;
    int aRowC = (aRowG < M) ? aRowG : (M - 1);
    int bRowG = n0 + arow;                     // N is always multiple of 128

    uint32_t aDst[2], bDst[2];
    #pragma unroll
    for (int s = 0; s < 2; ++s) {
        aDst[s] = smem_u32(&smA[s][arow * ASTR + ahalf * 16]);
        bDst[s] = smem_u32(&smB[s][arow * BSTR + ahalf * 16]);
    }

    float acc[4][4][4];
    #pragma unroll
    for (int i = 0; i < 4; ++i)
        #pragma unroll
        for (int j = 0; j < 4; ++j)
            #pragma unroll
            for (int r = 0; r < 4; ++r) acc[i][j][r] = 0.f;

    uint4 ra0, ra1, rb0, rb1;   // used only by FUSE register path

    if (FUSE) {
        const float* x = (const float*)Av + (size_t)aRowC * K + ahalf * 16;
        const float* p = A2 + (size_t)aRowC * K + ahalf * 16;
        float4 x0 = *(const float4*)(x), x1 = *(const float4*)(x + 4);
        float4 x2 = *(const float4*)(x + 8), x3 = *(const float4*)(x + 12);
        float4 p0 = *(const float4*)(p), p1 = *(const float4*)(p + 4);
        float4 p2 = *(const float4*)(p + 8), p3 = *(const float4*)(p + 12);
        ra0.x = packh2(x0.x + p0.x, x0.y + p0.y); ra0.y = packh2(x0.z + p0.z, x0.w + p0.w);
        ra0.z = packh2(x1.x + p1.x, x1.y + p1.y); ra0.w = packh2(x1.z + p1.z, x1.w + p1.w);
        ra1.x = packh2(x2.x + p2.x, x2.y + p2.y); ra1.y = packh2(x2.z + p2.z, x2.w + p2.w);
        ra1.z = packh2(x3.x + p3.x, x3.y + p3.y); ra1.w = packh2(x3.z + p3.z, x3.w + p3.w);
        const uint4* bG = (const uint4*)&Bt[(size_t)bRowG * K + ahalf * 16];
        rb0 = bG[0]; rb1 = bG[1];
    } else {
        const char* aS = (const char*)((const __half*)Av + (size_t)aRowC * K + ahalf * 16);
        const char* bS = (const char*)&Bt[(size_t)bRowG * K + ahalf * 16];
        cpasync16(aDst[0],      aS);
        cpasync16(aDst[0] + 16, aS + 16);
        cpasync16(bDst[0],      bS);
        cpasync16(bDst[0] + 16, bS + 16);
        CP_COMMIT();
    }

    int sub = lane >> 3, lrow = lane & 7;

    for (int c = 0; c < NC; ++c) {
        int buf = c & 1;
        if (FUSE) {
            *reinterpret_cast<uint4*>(&smA[buf][arow * ASTR + ahalf * 16])     = ra0;
            *reinterpret_cast<uint4*>(&smA[buf][arow * ASTR + ahalf * 16 + 8]) = ra1;
            *reinterpret_cast<uint4*>(&smB[buf][arow * BSTR + ahalf * 16])     = rb0;
            *reinterpret_cast<uint4*>(&smB[buf][arow * BSTR + ahalf * 16 + 8]) = rb1;
            if (c + 1 < NC) {
                int ko = (c + 1) * 32 + ahalf * 16;
                const float* x = (const float*)Av + (size_t)aRowC * K + ko;
                const float* p = A2 + (size_t)aRowC * K + ko;
                float4 x0 = *(const float4*)(x), x1 = *(const float4*)(x + 4);
                float4 x2 = *(const float4*)(x + 8), x3 = *(const float4*)(x + 12);
                float4 p0 = *(const float4*)(p), p1 = *(const float4*)(p + 4);
                float4 p2 = *(const float4*)(p + 8), p3 = *(const float4*)(p + 12);
                ra0.x = packh2(x0.x + p0.x, x0.y + p0.y); ra0.y = packh2(x0.z + p0.z, x0.w + p0.w);
                ra0.z = packh2(x1.x + p1.x, x1.y + p1.y); ra0.w = packh2(x1.z + p1.z, x1.w + p1.w);
                ra1.x = packh2(x2.x + p2.x, x2.y + p2.y); ra1.y = packh2(x2.z + p2.z, x2.w + p2.w);
                ra1.z = packh2(x3.x + p3.x, x3.y + p3.y); ra1.w = packh2(x3.z + p3.z, x3.w + p3.w);
                const uint4* bG = (const uint4*)&Bt[(size_t)bRowG * K + ko];
                rb0 = bG[0]; rb1 = bG[1];
            }
            __syncthreads();
        } else {
            if (c + 1 < NC) {
                int ko = (c + 1) * 32 + ahalf * 16;
                int nxt = (c + 1) & 1;
                const char* aS = (const char*)((const __half*)Av + (size_t)aRowC * K + ko);
                const char* bS = (const char*)&Bt[(size_t)bRowG * K + ko];
                cpasync16(aDst[nxt],      aS);
                cpasync16(aDst[nxt] + 16, aS + 16);
                cpasync16(bDst[nxt],      bS);
                cpasync16(bDst[nxt] + 16, bS + 16);
                CP_COMMIT();
                CP_WAIT1();
            } else {
                CP_WAIT0();
            }
            __syncthreads();
        }

        const __half* As = smA[buf];
        const __half* Bs = smB[buf];
        #pragma unroll
        for (int ks = 0; ks < 2; ++ks) {
            uint32_t af[4][4];
            #pragma unroll
            for (int mt = 0; mt < 4; ++mt) {
                int r = wm * 64 + mt * 16 + ((sub & 1) << 3) + lrow;
                int col = ks * 16 + ((sub >> 1) << 3);
                LDSM4(af[mt], smem_u32(&As[r * ASTR + col]));
            }
            uint32_t bf[4][2];
            #pragma unroll
            for (int g = 0; g < 2; ++g) {
                int nr = wn * 32 + ((g * 2 + (sub >> 1)) << 3) + lrow;
                int col = ks * 16 + ((sub & 1) << 3);
                uint32_t t[4];
                LDSM4(t, smem_u32(&Bs[nr * BSTR + col]));
                bf[g * 2 + 0][0] = t[0]; bf[g * 2 + 0][1] = t[1];
                bf[g * 2 + 1][0] = t[2]; bf[g * 2 + 1][1] = t[3];
            }
            #pragma unroll
            for (int mt = 0; mt < 4; ++mt)
                #pragma unroll
                for (int nt = 0; nt < 4; ++nt)
                    mma_f16(acc[mt][nt], af[mt], bf[nt]);
        }
        __syncthreads();
    }

    #pragma unroll
    for (int mt = 0; mt < 4; ++mt) {
        int r0 = m0 + wm * 64 + mt * 16 + (lane >> 2);
        int r1 = r0 + 8;
        #pragma unroll
        for (int nt = 0; nt < 4; ++nt) {
            int cb = n0 + wn * 32 + nt * 8 + 2 * (lane & 3);
            float b0 = bias[cb], b1 = bias[cb + 1];
            float v0 = acc[mt][nt][0] + b0;
            float v1 = acc[mt][nt][1] + b1;
            float v2 = acc[mt][nt][2] + b0;
            float v3 = acc[mt][nt][3] + b1;
            if (RELU) {
                v0 = fmaxf(v0, 0.f); v1 = fmaxf(v1, 0.f);
                v2 = fmaxf(v2, 0.f); v3 = fmaxf(v3, 0.f);
            }
            if (HALF_OUT) {
                __half* Ch = (__half*)Cv;
                if (r0 < M)
                    *reinterpret_cast<__half2*>(&Ch[(size_t)r0 * N + cb]) = __floats2half2_rn(v0, v1);
                if (r1 < M)
                    *reinterpret_cast<__half2*>(&Ch[(size_t)r1 * N + cb]) = __floats2half2_rn(v2, v3);
            } else {
                float* Cf = (float*)Cv;
                if (r0 < M)
                    *reinterpret_cast<float2*>(&Cf[(size_t)r0 * N + cb]) = make_float2(v0, v1);
                if (r1 < M)
                    *reinterpret_cast<float2*>(&Cf[(size_t)r1 * N + cb]) = make_float2(v2, v3);
            }
        }
    }
}

// ---------------- deformable attention sampling ----------------
__global__ void deform_kernel(const __half* __restrict__ pvalh, const float* __restrict__ pol,
                              const float* __restrict__ pref, __half* __restrict__ psamph) {
    int gwarp = (blockIdx.x * blockDim.x + threadIdx.x) >> 5;
    int lane = threadIdx.x & 31;
    if (gwarp >= BATCH * QTOT * NH) return;
    int h = gwarp % NH;
    int q = (gwarp / NH) % QTOT;
    int b = gwarp / (NH * QTOT);
    size_t tok = (size_t)b * QTOT + q;

    const float* orow = &pol[tok * 384 + h * 32];
    const float* lrow = &pol[tok * 384 + 256 + h * 16];

    float lg[16];
    float mx = -1e30f;
    #pragma unroll
    for (int i = 0; i < 16; ++i) { lg[i] = __ldg(&lrow[i]); mx = fmaxf(mx, lg[i]); }
    float ssum = 0.f;
    #pragma unroll
    for (int i = 0; i < 16; ++i) { lg[i] = expf(lg[i] - mx); ssum += lg[i]; }
    float inv = 1.f / ssum;

    float rx = pref[2 * q];
    float ry = pref[2 * q + 1];

    float acc = 0.f;
    #pragma unroll
    for (int p = 0; p < 16; ++p) {
        int l = p >> 2;
        float w  = lg[p] * inv;
        float ox = __ldg(&orow[2 * p]);
        float oy = __ldg(&orow[2 * p + 1]);
        int Wl = c_W[l], Hl = c_H[l];
        float fw = (float)Wl, fh = (float)Hl;
        float x = (rx + ox / fw) * fw - 0.5f;
        float y = (ry + oy / fh) * fh - 0.5f;
        float x0f = floorf(x), y0f = floorf(y);
        int x0 = (int)x0f, y0 = (int)y0f;
        float fx = x - x0f, fy = y - y0f;
        size_t base = (size_t)b * QTOT + c_start[l];
        #pragma unroll
        for (int dy = 0; dy < 2; ++dy) {
            #pragma unroll
            for (int dx = 0; dx < 2; ++dx) {
                int xi = x0 + dx, yi = y0 + dy;
                if (xi >= 0 && xi < Wl && yi >= 0 && yi < Hl) {
                    float bw = (dx ? fx : 1.f - fx) * (dy ? fy : 1.f - fy);
                    float v = __half2float(pvalh[(base + (size_t)yi * Wl + xi) * DMODEL + h * HD + lane]);
                    acc = fmaf(w * bw, v, acc);
                }
            }
        }
    }
    psamph[tok * DMODEL + h * HD + lane] = __float2half_rn(acc);
}

// ---------------- fused residual + layernorm ----------------
__global__ void ln_res_kernel(float* __restrict__ px, __half* __restrict__ pxh,
                              const float* __restrict__ y,
                              const float* __restrict__ g, const float* __restrict__ bb,
                              float* __restrict__ outp) {
    int warp = (blockIdx.x * blockDim.x + threadIdx.x) >> 5;
    int lane = threadIdx.x & 31;
    if (warp >= BQ) return;
    size_t base = (size_t)warp * DMODEL;
    float v[8];
    float s = 0.f, s2 = 0.f;
    #pragma unroll
    for (int k = 0; k < 8; ++k) {
        int d = k * 32 + lane;
        v[k] = px[base + d] + y[base + d];
        s += v[k];
        s2 += v[k] * v[k];
    }
    s = wredsum(s);
    s2 = wredsum(s2);
    float m = s * (1.f / DMODEL);
    float var = s2 * (1.f / DMODEL) - m * m;
    float rstd = rsqrtf(var + 1e-5f);
    #pragma unroll
    for (int k = 0; k < 8; ++k) {
        int d = k * 32 + lane;
        float o = (v[k] - m) * rstd * g[d] + bb[d];
        px[base + d]  = o;
        pxh[base + d] = __float2half_rn(o);
        if (outp) outp[base + d] = o;
    }
}

// ---------------- launch ----------------
extern "C" void kernel_launch(void* const* d_in, const int* in_sizes, int n_in,
                              void* d_out, int out_size) {
    (void)n_in; (void)out_size;

    float *px, *ppos, *pol, *pattn, *pff2, *pref, *pbc;
    __half *pxh, *pvalh, *psamph, *pffh, *pwt;
    cudaGetSymbolAddress((void**)&px,    g_x);
    cudaGetSymbolAddress((void**)&ppos,  g_pos);
    cudaGetSymbolAddress((void**)&pol,   g_offlog);
    cudaGetSymbolAddress((void**)&pattn, g_attnout);
    cudaGetSymbolAddress((void**)&pff2,  g_ff2);
    cudaGetSymbolAddress((void**)&pref,  g_ref);
    cudaGetSymbolAddress((void**)&pbc,   g_bcomb);
    cudaGetSymbolAddress((void**)&pxh,   g_xh);
    cudaGetSymbolAddress((void**)&pvalh, g_valh);
    cudaGetSymbolAddress((void**)&psamph,g_samph);
    cudaGetSymbolAddress((void**)&pffh,  g_ffh);
    cudaGetSymbolAddress((void**)&pwt,   g_wt);

    bool interleaved = (in_sizes[1] == in_sizes[0]);
    const float* src[4];
    const float* pos[4];
    for (int i = 0; i < 4; ++i) {
        if (interleaved) {
            src[i] = (const float*)d_in[2 * i];
            pos[i] = (const float*)d_in[2 * i + 1];
        } else {
            src[i] = (const float*)d_in[i];
            pos[i] = (const float*)d_in[4 + i];
        }
    }
    const float* level_embed = (const float*)d_in[8];
    const float* Woff  = (const float*)d_in[9];
    const float* boff  = (const float*)d_in[10];
    const float* Wattn = (const float*)d_in[11];
    const float* battn = (const float*)d_in[12];
    const float* Wv    = (const float*)d_in[13];
    const float* bv    = (const float*)d_in[14];
    const float* Wo    = (const float*)d_in[15];
    const float* bo    = (const float*)d_in[16];
    const float* g1    = (const float*)d_in[17];
    const float* b1    = (const float*)d_in[18];
    const float* W1    = (const float*)d_in[19];
    const float* bb1   = (const float*)d_in[20];
    const float* W2    = (const float*)d_in[21];
    const float* bb2   = (const float*)d_in[22];
    const float* g2    = (const float*)d_in[23];
    const float* b2    = (const float*)d_in[24];
    float* out = (float*)d_out;

    const int hws[4]    = {10000, 2500, 625, 169};
    const int starts[4] = {0, 10000, 12500, 13125};

    for (int l = 0; l < 4; ++l) {
        int total = BATCH * hws[l] * DMODEL;
        flatten_kernel<<<(total + 255) / 256, 256>>>(px, pxh, ppos, src[l], pos[l],
                                                     level_embed + l * DMODEL, starts[l], hws[l]);
    }
    ref_kernel<<<(QTOT + 255) / 256, 256>>>(pref);

    transpose_woa<<<(NLAYERS * 384 * 256 + 255) / 256, 256>>>(pwt, Woff, Wattn);
    transpose_nl<<<(NLAYERS * 256 * 256 + 255) / 256, 256>>>(pwt + OFF_WV, Wv, 256, 256);
    transpose_nl<<<(NLAYERS * 256 * 256 + 255) / 256, 256>>>(pwt + OFF_WO, Wo, 256, 256);
    transpose_nl<<<(NLAYERS * 1024 * 256 + 255) / 256, 256>>>(pwt + OFF_W1, W1, 256, 1024);
    transpose_nl<<<(NLAYERS * 256 * 1024 + 255) / 256, 256>>>(pwt + OFF_W2, W2, 1024, 256);
    bias_comb_kernel<<<(NLAYERS * 384 + 255) / 256, 256>>>(pbc, boff, battn);

    const int mblocks = (BQ + TM - 1) / TM;                    // 208
    const int warp_grid_deform = (BATCH * QTOT * NH + 7) / 8;
    const int warp_grid_ln = (BQ + 7) / 8;

    for (int l = 0; l < NLAYERS; ++l) {
        __half* wt = pwt + (size_t)l * WT_LAYER;
        const float* bcomb_l = pbc + (size_t)l * 384;
        const float* bv_l    = bv  + (size_t)l * DMODEL;
        const float* bo_l    = bo  + (size_t)l * DMODEL;
        const float* bb1_l   = bb1 + (size_t)l * DFF;
        const float* bb2_l   = bb2 + (size_t)l * DMODEL;

        gemm_h_kernel<false, false, true><<<dim3(mblocks, 384 / TN), 256>>>(
            px, ppos, wt + OFF_WOA, bcomb_l, pol, BQ, 384, 256);
        gemm_h_kernel<false, true, false><<<dim3(mblocks, 256 / TN), 256>>>(
            pxh, nullptr, wt + OFF_WV, bv_l, pvalh, BQ, 256, 256);

        deform_kernel<<<warp_grid_deform, 256>>>(pvalh, pol, pref, psamph);

        gemm_h_kernel<false, false, false><<<dim3(mblocks, 256 / TN), 256>>>(
            psamph, nullptr, wt + OFF_WO, bo_l, pattn, BQ, 256, 256);

        ln_res_kernel<<<warp_grid_ln, 256>>>(px, pxh, pattn,
                                             g1 + (size_t)l * DMODEL, b1 + (size_t)l * DMODEL,
                                             nullptr);

        gemm_h_kernel<true, true, false><<<dim3(mblocks, DFF / TN), 256>>>(
            pxh, nullptr, wt + OFF_W1, bb1_l, pffh, BQ, DFF, 256);
        gemm_h_kernel<false, false, false><<<dim3(mblocks, 256 / TN), 256>>>(
            pffh, nullptr, wt + OFF_W2, bb2_l, pff2, BQ, 256, 1024);

        ln_res_kernel<<<warp_grid_ln, 256>>>(px, pxh, pff2,
                                             g2 + (size_t)l * DMODEL, b2 + (size_t)l * DMODEL,
                                             (l == NLAYERS - 1) ? out : nullptr);
    }
}